// round 14
// baseline (speedup 1.0000x reference)
#include <cuda_runtime.h>
#include <cuda_pipeline.h>
#include <cstdint>
#include <math.h>

#define NVARS 1024
#define BATCH 64
#define KDIM  32
#define NIN   768
#define SWEEPS 10
#define PI_F 3.14159274101257324f
#define S 4

// dynamic smem layout (floats)
#define F_CBUF 0            // 12 half-rows * 512 (3-group x 4-row cp.async ring)
#define F_SVD  6144         // 11 * 1024 coupling tables, distance 1..11 (CTA0 uses)
#define F_PT   17408        // 3 * 4 * 512 local partials [slot][s][warp16][lane]
#define F_RSUM 23552        // 2 * 4 * 32 pre-reduced CTA1 partials (on CTA0)
#define F_VNB  23808        // 2 * 4 * 32 vn broadcast
#define F_LST  24064        // 1024 ushort = 512 floats
#define SMEM_FLOATS 24576
#define SMEM_BYTES (SMEM_FLOATS * 4)   // 96 KB

// ---------------- persistent scratch (no runtime allocation) ----------------
__device__ float V_g[BATCH * NVARS * KDIM];     // 8 MB
__device__ float VH_g[BATCH * NVARS * KDIM];    // 8 MB value-history by list position
__device__ float v0_g[BATCH * KDIM];
__device__ unsigned short list_g[BATCH * NVARS];
__device__ int cnt_g[BATCH];

// ---------------- f32x2 helpers ----------------
__device__ __forceinline__ void ffma2(unsigned long long &d, unsigned long long a,
                                      unsigned long long b) {
    asm("fma.rn.f32x2 %0, %1, %2, %3;" : "=l"(d) : "l"(a), "l"(b), "l"(d));
}
__device__ __forceinline__ void fadd2(unsigned long long &d, unsigned long long a,
                                      unsigned long long b) {
    asm("add.rn.f32x2 %0, %1, %2;" : "=l"(d) : "l"(a), "l"(b));
}
__device__ __forceinline__ unsigned long long pk2(float lo, float hi) {
    unsigned long long r;
    asm("mov.b64 %0, {%1, %2};" : "=l"(r) : "f"(lo), "f"(hi));
    return r;
}
__device__ __forceinline__ void up2(unsigned long long v, float &lo, float &hi) {
    asm("mov.b64 {%0, %1}, %2;" : "=f"(lo), "=f"(hi) : "l"(v));
}

__device__ __forceinline__ float warp_sum(float v) {
#pragma unroll
    for (int off = 16; off; off >>= 1)
        v += __shfl_xor_sync(0xffffffffu, v, off);
    return v;
}

__device__ __forceinline__ uint32_t smem_u32(const void* p) {
    uint32_t a;
    asm("{ .reg .u64 t; cvta.to.shared.u64 t, %1; cvt.u32.u64 %0, t; }"
        : "=r"(a) : "l"(p));
    return a;
}

// store one f32 into the peer CTA's smem at the same offset
__device__ __forceinline__ void sts_remote(uint32_t laddr, uint32_t trank, float v) {
    uint32_t raddr;
    asm("mapa.shared::cluster.u32 %0, %1, %2;" : "=r"(raddr) : "r"(laddr), "r"(trank));
    asm volatile("st.shared::cluster.b32 [%0], %1;"
                 :: "r"(raddr), "r"(__float_as_uint(v)) : "memory");
}

#define CLUSTER_SYNC() do { \
    asm volatile("barrier.cluster.arrive.aligned;" ::: "memory"); \
    asm volatile("barrier.cluster.wait.aligned;" ::: "memory"); \
} while (0)

// 32-row dot: 32 floats (8 ulonglong2) against v2[16]
__device__ __forceinline__ float dot_row16(const ulonglong2* __restrict__ Cp,
                                           const unsigned long long (&v2)[16]) {
    unsigned long long a0 = 0ull, a1 = 0ull, a2 = 0ull, a3 = 0ull;
#pragma unroll
    for (int q = 0; q < 8; q++) {
        ulonglong2 cc = Cp[q];
        ffma2(((q & 1) ? a2 : a0), cc.x, v2[2 * q]);
        ffma2(((q & 1) ? a3 : a1), cc.y, v2[2 * q + 1]);
    }
    fadd2(a0, a0, a2); fadd2(a1, a1, a3); fadd2(a0, a0, a1);
    float x, y; up2(a0, x, y);
    return x + y;
}

// predicated-chain insert over 16 register pairs
__device__ __forceinline__ void insert16(unsigned long long (&v2)[16], int j, float vn) {
    int p0 = j >> 1;
#pragma unroll
    for (int p = 0; p < 16; p++)
        if (p == p0) {
            float x, y; up2(v2[p], x, y);
            if (j & 1) y = vn; else x = vn;
            v2[p] = pk2(x, y);
        }
}

// ---------------- threefry2x32 core, exact JAX schedule ----------------
__device__ __forceinline__ void tf2x32(unsigned k0, unsigned k1,
                                       unsigned x0, unsigned x1,
                                       unsigned &y0, unsigned &y1) {
    unsigned ks2 = k0 ^ k1 ^ 0x1BD11BDAu;
    x0 += k0; x1 += k1;
#define TFR(r) { x0 += x1; x1 = (x1 << r) | (x1 >> (32 - r)); x1 ^= x0; }
    TFR(13) TFR(15) TFR(26) TFR(6)  x0 += k1;  x1 += ks2 + 1u;
    TFR(17) TFR(29) TFR(16) TFR(24) x0 += ks2; x1 += k0 + 2u;
    TFR(13) TFR(15) TFR(26) TFR(6)  x0 += k0;  x1 += k1 + 3u;
    TFR(17) TFR(29) TFR(16) TFR(24) x0 += k1;  x1 += ks2 + 4u;
    TFR(13) TFR(15) TFR(26) TFR(6)  x0 += ks2; x1 += k0 + 5u;
#undef TFR
    y0 = x0; y1 = x1;
}

// PARTITIONABLE threefry (modern JAX default)
__device__ __forceinline__ void derive_keys(unsigned &k1a, unsigned &k1b,
                                            unsigned &k2a, unsigned &k2b) {
    tf2x32(0u, 42u, 0u, 0u, k1a, k1b);
    tf2x32(0u, 42u, 0u, 1u, k2a, k2b);
}

__device__ __forceinline__ unsigned tf_bits(unsigned ka, unsigned kb, unsigned e) {
    unsigned y0, y1;
    tf2x32(ka, kb, 0u, e, y0, y1);
    return y0 ^ y1;
}

__device__ __forceinline__ float bits_to_normal(unsigned bits) {
    float u01 = __fadd_rn(__uint_as_float((bits >> 9) | 0x3F800000u), -1.0f);
    float u = __fadd_rn(__fmul_rn(u01, 2.0f), -0.99999994f);
    u = fmaxf(u, -0.99999994f);
    float x = u;
    float xx = __fmul_rn(x, x);
    float w = -log1pf(-xx);
    float p;
    if (w < 5.0f) {
        w = __fadd_rn(w, -2.5f);
        p = 2.81022636e-08f;
        p = __fadd_rn(__fmul_rn(p, w), 3.43273939e-07f);
        p = __fadd_rn(__fmul_rn(p, w), -3.5233877e-06f);
        p = __fadd_rn(__fmul_rn(p, w), -4.39150654e-06f);
        p = __fadd_rn(__fmul_rn(p, w), 0.00021858087f);
        p = __fadd_rn(__fmul_rn(p, w), -0.00125372503f);
        p = __fadd_rn(__fmul_rn(p, w), -0.00417768164f);
        p = __fadd_rn(__fmul_rn(p, w), 0.246640727f);
        p = __fadd_rn(__fmul_rn(p, w), 1.50140941f);
    } else {
        w = __fadd_rn(sqrtf(w), -3.0f);
        p = -0.000200214257f;
        p = __fadd_rn(__fmul_rn(p, w), 0.000100950558f);
        p = __fadd_rn(__fmul_rn(p, w), 0.00134934322f);
        p = __fadd_rn(__fmul_rn(p, w), -0.00367342844f);
        p = __fadd_rn(__fmul_rn(p, w), 0.00573950773f);
        p = __fadd_rn(__fmul_rn(p, w), -0.0076224613f);
        p = __fadd_rn(__fmul_rn(p, w), 0.00943887047f);
        p = __fadd_rn(__fmul_rn(p, w), 1.00167406f);
        p = __fadd_rn(__fmul_rn(p, w), 2.83297682f);
    }
    return __fmul_rn(1.41421354f, __fmul_rn(p, x));
}

// ---------------- fused init kernel: one CTA per batch, 1024 threads ----------------
__global__ void __launch_bounds__(1024, 1)
init_kernel(const float* __restrict__ z, const int* __restrict__ is_input) {
    __shared__ float v0s[32];
    const int b = blockIdx.x;
    const int w = threadIdx.x >> 5;
    const int l = threadIdx.x & 31;
    unsigned k1a, k1b, k2a, k2b; derive_keys(k1a, k1b, k2a, k2b);

    if (w == 0) {
        float n = bits_to_normal(tf_bits(k1a, k1b, (unsigned)(b * 32 + l)));
        float ss = warp_sum(__fmul_rn(n, n));
        float v0 = n / sqrtf(ss);
        v0s[l] = v0;
        v0_g[b * 32 + l] = v0;
    }
    __syncthreads();
    float v0l = v0s[l];

#pragma unroll 1
    for (int k = 0; k < 32; k++) {
        int n = w * 32 + k;
        unsigned e = ((unsigned)(b * 1024 + n)) * 32u + (unsigned)l;
        float r = bits_to_normal(tf_bits(k2a, k2b, e));
        float d = warp_sum(__fmul_rn(r, v0l));
        float rp = __fadd_rn(r, -__fmul_rn(d, v0l));
        float nr = sqrtf(warp_sum(__fmul_rn(rp, rp)));
        float R = rp / nr;

        float zf; int ii;
        if (n == 0)        { zf = 1.0f; ii = 1; }
        else if (n <= NIN) { zf = z[b * NIN + n - 1]; ii = is_input[b * NIN + n - 1]; }
        else               { zf = 0.0f; ii = 0; }

        float V;
        if (ii > 0) {
            float x = __fmul_rn(PI_F, zf);
            V = __fadd_rn(__fmul_rn(-cosf(x), v0l), __fmul_rn(sinf(x), R));
        } else {
            V = R;
        }
        if (n == 0) V = v0l;
        V_g[((size_t)b * 1024 + n) * 32 + l] = V;
    }

    // free list (warp 31)
    if (w == 31) {
        int m = 0;
        for (int base = 1; base < 1024; base += 32) {
            int n = base + l;
            bool f = (n < 1024) && (n > NIN || is_input[b * NIN + n - 1] == 0);
            unsigned msk = __ballot_sync(0xffffffffu, f);
            if (f) {
                int pos = m + __popc(msk & ((1u << l) - 1u));
                list_g[b * 1024 + pos] = (unsigned short)n;
            }
            m += __popc(msk);
        }
        if (l == 0) cnt_g[b] = m;
    }
    __syncthreads();

    // VH fill: VH[b][m] = V_init[b][lst[m]]
    int c = cnt_g[b];
    for (int m = w; m < c; m += 32) {
        int i = list_g[b * 1024 + m];
        VH_g[((size_t)b * 1024 + m) * 32 + l] = V_g[((size_t)b * 1024 + i) * 32 + l];
    }
}

// ---------------- mix kernel: 2-CTA cluster, 16 dot warps x 32 rows, S=4, depth-2 ----------------
__global__ void __launch_bounds__(544, 1) __cluster_dims__(2, 1, 1)
mix_kernel(const float* __restrict__ C,
           const float* __restrict__ z,
           const int* __restrict__ is_input,
           float* __restrict__ out) {
    extern __shared__ __align__(16) float sm[];
    unsigned short* lstS = (unsigned short*)&sm[F_LST];

    uint32_t rank;
    asm("mov.u32 %0, %%cluster_ctarank;" : "=r"(rank));
    const int b = blockIdx.x >> 1;
    const int tid = threadIdx.x;
    const int w = tid >> 5;           // 0..16
    const int l = tid & 31;
    const bool dotw = (w < 16);
    const bool redw = (rank == 0) && (w == 16);
    const bool prew = (rank == 1) && (w == 16);
    const uint32_t smb = smem_u32(sm);

    __shared__ int scnt;
    for (int idx = tid; idx < 1024; idx += 544)
        lstS[idx] = list_g[b * 1024 + idx];
    if (tid == 0) scnt = cnt_g[b];
    __syncthreads();
    const int cnt = scnt;
    const int total = cnt * SWEEPS;
    const int P = (total + S - 1) / S;

    // coupling tables (CTA0 only): svd[d][m] = C[lst[(m+d+1)%cnt], lst[m]], dist 1..11
    if (rank == 0) {
        for (int t = tid; t < 11 * cnt; t += 544) {
            int d = t / cnt;
            int m = t - d * cnt;
            int mp = m + d + 1; if (mp >= cnt) mp -= cnt;
            sm[F_SVD + d * 1024 + m] =
                __ldg(C + (size_t)lstS[mp] * NVARS + lstS[m]);
        }
    }

    // V registers: warp w owns rows [rank*512 + 32w, +32), lane l = column l
    unsigned long long v2[16];
    const int rowbase = (int)rank * 512 + w * 32;
    if (dotw) {
#pragma unroll
        for (int p = 0; p < 16; p++) {
            int row = rowbase + 2 * p;
            v2[p] = pk2(V_g[((size_t)b * 1024 + row) * 32 + l],
                        V_g[((size_t)b * 1024 + row + 1) * 32 + l]);
        }
    }
    __syncthreads();

    // staging: tid<512: half-row s = tid>>7, one 16B chunk at (tid&127)*4
    const int st_s = tid >> 7;
    const int st_c = (tid & 127) * 4;

    // prologue staging: G2 -> slot 2, G3 -> slot 0
    if (tid < 512) {
        int mq = (2 * S + st_s) % cnt;
        const float* src = C + (size_t)lstS[mq] * NVARS + rank * 512;
        __pipeline_memcpy_async(&sm[F_CBUF + (2 * 4 + st_s) * 512 + st_c], src + st_c, 16);
    }
    __pipeline_commit();
    if (tid < 512) {
        int mq = (3 * S + st_s) % cnt;
        const float* src = C + (size_t)lstS[mq] * NVARS + rank * 512;
        __pipeline_memcpy_async(&sm[F_CBUF + (0 * 4 + st_s) * 512 + st_c], src + st_c, 16);
    }
    __pipeline_commit();

    // prologue dots: G0 -> local pT slot 0, G1 -> slot 1 (from gmem, init V)
    if (dotw) {
#pragma unroll
        for (int s = 0; s < S; s++) {
            const ulonglong2* Cp = reinterpret_cast<const ulonglong2*>(
                C + (size_t)lstS[s] * NVARS + rowbase);
            sm[F_PT + 0 * 2048 + s * 512 + w * 32 + l] = dot_row16(Cp, v2);
        }
#pragma unroll
        for (int s = 0; s < S; s++) {
            int mq = (S + s) % cnt;
            const ulonglong2* Cp = reinterpret_cast<const ulonglong2*>(
                C + (size_t)lstS[mq] * NVARS + rowbase);
            sm[F_PT + 1 * 2048 + s * 512 + w * 32 + l] = dot_row16(Cp, v2);
        }
    }
    __syncthreads();   // local pT visible to warp 16

    // prologue pre-reduce: CTA1 w16 pushes G0 pre-sum to CTA0 rsum slot 0
    if (prew) {
#pragma unroll
        for (int s = 0; s < S; s++) {
            const float* pr = &sm[F_PT + 0 * 2048 + s * 512];
            float g = 0.0f;
            {
                float t0 = pr[0*32+l],  t1 = pr[1*32+l],  t2 = pr[2*32+l],  t3 = pr[3*32+l];
                float t4 = pr[4*32+l],  t5 = pr[5*32+l],  t6 = pr[6*32+l],  t7 = pr[7*32+l];
                float t8 = pr[8*32+l],  t9 = pr[9*32+l],  ta = pr[10*32+l], tb = pr[11*32+l];
                float tc = pr[12*32+l], td = pr[13*32+l], te = pr[14*32+l], tf = pr[15*32+l];
                g = (((t0+t1)+(t2+t3)) + ((t4+t5)+(t6+t7)))
                  + (((t8+t9)+(ta+tb)) + ((tc+td)+(te+tf)));
            }
            sts_remote(smb + (F_RSUM + 0 * 128 + s * 32 + l) * 4, 0, g);
        }
    }

    // reducer state
    float dvP1[S] = {0.f, 0.f, 0.f, 0.f};   // dv of group p-1
    float dvP2[S] = {0.f, 0.f, 0.f, 0.f};   // dv of group p-2
    float vold_cur[S];
    if (redw) {
#pragma unroll
        for (int s = 0; s < S; s++)
            vold_cur[s] = VH_g[((size_t)b * 1024 + s) * 32 + l];
    }

    __pipeline_wait_prior(1);
    CLUSTER_SYNC();

    int m_prev2 = 0, m_prev = 0, m_cur = 0;
    int m_n1 = S % cnt, m_stage = (4 * S) % cnt;

    for (int p = 0; p < P; p++) {
        // stage G_{p+4} into cbuf slot (p+1)%3
        if (tid < 512) {
            int mq = m_stage + st_s; if (mq >= cnt) mq -= cnt;
            const float* src = C + (size_t)lstS[mq] * NVARS + rank * 512;
            __pipeline_memcpy_async(&sm[F_CBUF + (((p + 1) % 3) * 4 + st_s) * 512 + st_c],
                                    src + st_c, 16);
        }
        __pipeline_commit();

        if (dotw) {
            // apply vn(G_{p-1})
            if (p > 0) {
#pragma unroll
                for (int s = 0; s < S; s++) {
                    int mp = m_prev + s; if (mp >= cnt) mp -= cnt;
                    int i = lstS[mp];
                    if ((i >> 5) == (int)rank * 16 + w)
                        insert16(v2, i & 31, sm[F_VNB + ((p - 1) & 1) * 128 + s * 32 + l]);
                }
            }
            // dots for G_{p+2} from cbuf slot (p+2)%3 -> local pT slot (p+2)%3
            int slotr = ((p + 2) % 3) * 4;
            int slotw = ((p + 2) % 3) * 2048;
#pragma unroll
            for (int s = 0; s < S; s++) {
                const ulonglong2* Cs = reinterpret_cast<const ulonglong2*>(
                    &sm[F_CBUF + (slotr + s) * 512 + w * 32]);
                sm[F_PT + slotw + s * 512 + w * 32 + l] = dot_row16(Cs, v2);
            }
        } else if (prew) {
            // CTA1: pre-reduce local partials of G_{p+1} -> CTA0 rsum[(p+1)&1]
            int slot = ((p + 1) % 3) * 2048;
#pragma unroll
            for (int s = 0; s < S; s++) {
                const float* pr = &sm[F_PT + slot + s * 512];
                float t0 = pr[0*32+l],  t1 = pr[1*32+l],  t2 = pr[2*32+l],  t3 = pr[3*32+l];
                float t4 = pr[4*32+l],  t5 = pr[5*32+l],  t6 = pr[6*32+l],  t7 = pr[7*32+l];
                float t8 = pr[8*32+l],  t9 = pr[9*32+l],  ta = pr[10*32+l], tb = pr[11*32+l];
                float tc = pr[12*32+l], td = pr[13*32+l], te = pr[14*32+l], tf = pr[15*32+l];
                float rs = (((t0+t1)+(t2+t3)) + ((t4+t5)+(t6+t7)))
                         + (((t8+t9)+(ta+tb)) + ((tc+td)+(te+tf)));
                sts_remote(smb + (F_RSUM + ((p + 1) & 1) * 128 + s * 32 + l) * 4, 0, rs);
            }
        } else if (redw) {
            // prefetch vold for G_{p+1}
            float vold_nxt[S];
#pragma unroll
            for (int s = 0; s < S; s++) {
                int mq = m_n1 + s; if (mq >= cnt) mq -= cnt;
                vold_nxt[s] = VH_g[((size_t)b * 1024 + mq) * 32 + l];
            }
            // base: 16 local partials + remote pre-sum + two-group-back corrections
            float base[S];
            int slotl = (p % 3) * 2048;
#pragma unroll
            for (int s = 0; s < S; s++) {
                const float* pr = &sm[F_PT + slotl + s * 512];
                float t0 = pr[0*32+l],  t1 = pr[1*32+l],  t2 = pr[2*32+l],  t3 = pr[3*32+l];
                float t4 = pr[4*32+l],  t5 = pr[5*32+l],  t6 = pr[6*32+l],  t7 = pr[7*32+l];
                float t8 = pr[8*32+l],  t9 = pr[9*32+l],  ta = pr[10*32+l], tb = pr[11*32+l];
                float tc = pr[12*32+l], td = pr[13*32+l], te = pr[14*32+l], tf = pr[15*32+l];
                float g = (((t0+t1)+(t2+t3)) + ((t4+t5)+(t6+t7)))
                        + (((t8+t9)+(ta+tb)) + ((tc+td)+(te+tf)));
                g += sm[F_RSUM + (p & 1) * 128 + s * 32 + l];
#pragma unroll
                for (int sp = 0; sp < S; sp++) {
                    int d2 = 2 * S + s - sp;            // 5..11
                    int mq2 = m_prev2 + sp; if (mq2 >= cnt) mq2 -= cnt;
                    g = fmaf(sm[F_SVD + (d2 - 1) * 1024 + mq2], dvP2[sp], g);
                    int d1 = S + s - sp;                // 1..7
                    int mq1 = m_prev + sp; if (mq1 >= cnt) mq1 -= cnt;
                    g = fmaf(sm[F_SVD + (d1 - 1) * 1024 + mq1], dvP1[sp], g);
                }
                base[s] = g;
            }
            // serial chain: intra-group corrections + normalize
            float dv_new[S];
#pragma unroll
            for (int s = 0; s < S; s++) {
                float g = base[s];
#pragma unroll
                for (int sp = 0; sp < S; sp++)
                    if (sp < s) {
                        int d = s - sp;                 // 1..3
                        int mq = m_cur + sp; if (mq >= cnt) mq -= cnt;
                        g = fmaf(sm[F_SVD + (d - 1) * 1024 + mq], dv_new[sp], g);
                    }
                float ss = warp_sum(g * g);
                ss = fmaxf(ss, 1e-24f);
                float vn = -g * rsqrtf(ss);
                int voff = F_VNB + (p & 1) * 128 + s * 32 + l;
                sm[voff] = vn;
                sts_remote(smb + voff * 4, 1, vn);
                int mq = m_cur + s; if (mq >= cnt) mq -= cnt;
                VH_g[((size_t)b * 1024 + mq) * 32 + l] = vn;
                dv_new[s] = vn - vold_cur[s];
            }
#pragma unroll
            for (int s = 0; s < S; s++) {
                dvP2[s] = dvP1[s]; dvP1[s] = dv_new[s]; vold_cur[s] = vold_nxt[s];
            }
        }

        __pipeline_wait_prior(1);
        CLUSTER_SYNC();

        m_prev2 = m_prev; m_prev = m_cur; m_cur = m_n1;
        m_n1 += S; if (m_n1 >= cnt) m_n1 -= cnt;
        m_stage += S; if (m_stage >= cnt) m_stage -= cnt;
    }

    // apply pending last-phase updates (vn of G_{P-1})
    if (dotw) {
        int baseT = S * (P - 1);
        int basem = baseT % cnt;
        int vb = (P - 1) & 1;
#pragma unroll
        for (int s = 0; s < S; s++) {
            if (baseT + s < total) {
                int mp = basem + s; if (mp >= cnt) mp -= cnt;
                int i = lstS[mp];
                if ((i >> 5) == (int)rank * 16 + w)
                    insert16(v2, i & 31, sm[F_VNB + vb * 128 + s * 32 + l]);
            }
        }
    }

    // ---------------- epilogue: z_out[:, 1:769] ----------------
    if (dotw) {
        float v0l = v0_g[b * 32 + l];
        const float CLO = (float)(-1.0 + 1e-7);
        const float CHI = (float)( 1.0 - 1e-7);
#pragma unroll
        for (int j = 0; j < 32; j++) {
            int n = rowbase + j;
            if (n >= 1 && n <= NIN) {
                float x, y; up2(v2[j >> 1], x, y);
                float Vv = (j & 1) ? y : x;
                float d = warp_sum(__fmul_rn(Vv, v0l));
                if (l == 0) {
                    int idx = b * NIN + n - 1;
                    float res;
                    if (is_input[idx] != 0) {
                        res = z[idx];
                    } else {
                        float ca = fminf(fmaxf(-d, CLO), CHI);
                        res = acosf(ca) / PI_F;
                    }
                    out[idx] = res;
                }
            }
        }
    }
}

// ---------------- launcher ----------------
extern "C" void kernel_launch(void* const* d_in, const int* in_sizes, int n_in,
                              void* d_out, int out_size) {
    const float* C        = (const float*)d_in[0];
    const float* z        = (const float*)d_in[1];
    const int*   is_input = (const int*)d_in[2];
    float* out = (float*)d_out;

    cudaFuncSetAttribute(mix_kernel,
                         cudaFuncAttributeMaxDynamicSharedMemorySize, SMEM_BYTES);

    init_kernel<<<BATCH, 1024>>>(z, is_input);
    mix_kernel<<<2 * BATCH, 544, SMEM_BYTES>>>(C, z, is_input, out);
}

// round 15
// speedup vs baseline: 1.1463x; 1.1463x over previous
#include <cuda_runtime.h>
#include <cuda_pipeline.h>
#include <cstdint>
#include <math.h>

#define NVARS 1024
#define BATCH 64
#define KDIM  32
#define NIN   768
#define SWEEPS 10
#define PI_F 3.14159274101257324f
#define S 4

// dynamic smem layout (floats)
#define F_CBUF 0            // 12 half-rows * 512 (3-group x 4-row cp.async ring)
#define F_SVD  6144         // 11 * 1024 coupling tables, distance 1..11 (CTA0 uses)
#define F_PT   17408        // 3 * 4 * 256 local partials [slot3][s][warp8][lane]
#define F_RSUM 20480        // 3 * 4 * 32 pre-reduced CTA1 partials (on CTA0)
#define F_VNB  20864        // 4 * 4 * 32 vn broadcast (depth-4 ring)
#define F_LST  21376        // 1024 ushort = 512 floats
#define SMEM_FLOATS 21888
#define SMEM_BYTES (SMEM_FLOATS * 4)   // ~85.5 KB

// ---------------- persistent scratch (no runtime allocation) ----------------
__device__ float V_g[BATCH * NVARS * KDIM];     // 8 MB
__device__ float VH_g[BATCH * NVARS * KDIM];    // 8 MB value-history by list position
__device__ float v0_g[BATCH * KDIM];
__device__ unsigned short list_g[BATCH * NVARS];
__device__ int cnt_g[BATCH];

// ---------------- f32x2 helpers ----------------
__device__ __forceinline__ void ffma2(unsigned long long &d, unsigned long long a,
                                      unsigned long long b) {
    asm("fma.rn.f32x2 %0, %1, %2, %3;" : "=l"(d) : "l"(a), "l"(b), "l"(d));
}
__device__ __forceinline__ void fadd2(unsigned long long &d, unsigned long long a,
                                      unsigned long long b) {
    asm("add.rn.f32x2 %0, %1, %2;" : "=l"(d) : "l"(a), "l"(b));
}
__device__ __forceinline__ unsigned long long pk2(float lo, float hi) {
    unsigned long long r;
    asm("mov.b64 %0, {%1, %2};" : "=l"(r) : "f"(lo), "f"(hi));
    return r;
}
__device__ __forceinline__ void up2(unsigned long long v, float &lo, float &hi) {
    asm("mov.b64 {%0, %1}, %2;" : "=f"(lo), "=f"(hi) : "l"(v));
}

__device__ __forceinline__ float warp_sum(float v) {
#pragma unroll
    for (int off = 16; off; off >>= 1)
        v += __shfl_xor_sync(0xffffffffu, v, off);
    return v;
}

__device__ __forceinline__ uint32_t smem_u32(const void* p) {
    uint32_t a;
    asm("{ .reg .u64 t; cvta.to.shared.u64 t, %1; cvt.u32.u64 %0, t; }"
        : "=r"(a) : "l"(p));
    return a;
}

// store one f32 into the peer CTA's smem at the same offset
__device__ __forceinline__ void sts_remote(uint32_t laddr, uint32_t trank, float v) {
    uint32_t raddr;
    asm("mapa.shared::cluster.u32 %0, %1, %2;" : "=r"(raddr) : "r"(laddr), "r"(trank));
    asm volatile("st.shared::cluster.b32 [%0], %1;"
                 :: "r"(raddr), "r"(__float_as_uint(v)) : "memory");
}

// ---- mbarrier helpers ----
__device__ __forceinline__ void mbar_init(uint32_t addr, uint32_t count) {
    asm volatile("mbarrier.init.shared.b64 [%0], %1;" :: "r"(addr), "r"(count) : "memory");
}
__device__ __forceinline__ void mbar_arrive_local(uint32_t addr) {
    asm volatile("mbarrier.arrive.release.cta.shared::cta.b64 _, [%0];"
                 :: "r"(addr) : "memory");
}
__device__ __forceinline__ void mbar_arrive_remote(uint32_t laddr, uint32_t trank) {
    uint32_t raddr;
    asm("mapa.shared::cluster.u32 %0, %1, %2;" : "=r"(raddr) : "r"(laddr), "r"(trank));
    asm volatile("mbarrier.arrive.release.cluster.shared::cluster.b64 _, [%0];"
                 :: "r"(raddr) : "memory");
}
__device__ __forceinline__ void mbar_wait(uint32_t addr, uint32_t parity) {
    uint32_t done;
    asm volatile(
        "{\n\t.reg .pred p;\n\t"
        "mbarrier.try_wait.parity.acquire.cluster.shared::cta.b64 p, [%1], %2;\n\t"
        "selp.b32 %0, 1, 0, p;\n\t}"
        : "=r"(done) : "r"(addr), "r"(parity) : "memory");
    if (!done) {
        asm volatile(
            "{\n\t.reg .pred P1;\n\t"
            "WL_%=:\n\t"
            "mbarrier.try_wait.parity.acquire.cluster.shared::cta.b64 P1, [%0], %1, 0x989680;\n\t"
            "@P1 bra.uni WD_%=;\n\t"
            "bra.uni WL_%=;\n\t"
            "WD_%=:\n\t}"
            :: "r"(addr), "r"(parity) : "memory");
    }
}

#define CLUSTER_SYNC() do { \
    asm volatile("barrier.cluster.arrive.aligned;" ::: "memory"); \
    asm volatile("barrier.cluster.wait.aligned;" ::: "memory"); \
} while (0)

// half-row dot: 64 floats (16 ulonglong2) against v2[32]
__device__ __forceinline__ float dot_row(const ulonglong2* __restrict__ Cp,
                                         const unsigned long long (&v2)[32]) {
    unsigned long long a0 = 0ull, a1 = 0ull, a2 = 0ull, a3 = 0ull;
#pragma unroll
    for (int q = 0; q < 16; q++) {
        ulonglong2 cc = Cp[q];
        ffma2(((q & 1) ? a2 : a0), cc.x, v2[2 * q]);
        ffma2(((q & 1) ? a3 : a1), cc.y, v2[2 * q + 1]);
    }
    fadd2(a0, a0, a2); fadd2(a1, a1, a3); fadd2(a0, a0, a1);
    float x, y; up2(a0, x, y);
    return x + y;
}

// predicated-chain insert (verified form)
__device__ __forceinline__ void insert_pred(unsigned long long (&v2)[32], int j, float vn) {
    int p0 = j >> 1;
#pragma unroll
    for (int p = 0; p < 32; p++)
        if (p == p0) {
            float x, y; up2(v2[p], x, y);
            if (j & 1) y = vn; else x = vn;
            v2[p] = pk2(x, y);
        }
}

// ---------------- threefry2x32 core, exact JAX schedule ----------------
__device__ __forceinline__ void tf2x32(unsigned k0, unsigned k1,
                                       unsigned x0, unsigned x1,
                                       unsigned &y0, unsigned &y1) {
    unsigned ks2 = k0 ^ k1 ^ 0x1BD11BDAu;
    x0 += k0; x1 += k1;
#define TFR(r) { x0 += x1; x1 = (x1 << r) | (x1 >> (32 - r)); x1 ^= x0; }
    TFR(13) TFR(15) TFR(26) TFR(6)  x0 += k1;  x1 += ks2 + 1u;
    TFR(17) TFR(29) TFR(16) TFR(24) x0 += ks2; x1 += k0 + 2u;
    TFR(13) TFR(15) TFR(26) TFR(6)  x0 += k0;  x1 += k1 + 3u;
    TFR(17) TFR(29) TFR(16) TFR(24) x0 += k1;  x1 += ks2 + 4u;
    TFR(13) TFR(15) TFR(26) TFR(6)  x0 += ks2; x1 += k0 + 5u;
#undef TFR
    y0 = x0; y1 = x1;
}

// PARTITIONABLE threefry (modern JAX default)
__device__ __forceinline__ void derive_keys(unsigned &k1a, unsigned &k1b,
                                            unsigned &k2a, unsigned &k2b) {
    tf2x32(0u, 42u, 0u, 0u, k1a, k1b);
    tf2x32(0u, 42u, 0u, 1u, k2a, k2b);
}

__device__ __forceinline__ unsigned tf_bits(unsigned ka, unsigned kb, unsigned e) {
    unsigned y0, y1;
    tf2x32(ka, kb, 0u, e, y0, y1);
    return y0 ^ y1;
}

__device__ __forceinline__ float bits_to_normal(unsigned bits) {
    float u01 = __fadd_rn(__uint_as_float((bits >> 9) | 0x3F800000u), -1.0f);
    float u = __fadd_rn(__fmul_rn(u01, 2.0f), -0.99999994f);
    u = fmaxf(u, -0.99999994f);
    float x = u;
    float xx = __fmul_rn(x, x);
    float w = -log1pf(-xx);
    float p;
    if (w < 5.0f) {
        w = __fadd_rn(w, -2.5f);
        p = 2.81022636e-08f;
        p = __fadd_rn(__fmul_rn(p, w), 3.43273939e-07f);
        p = __fadd_rn(__fmul_rn(p, w), -3.5233877e-06f);
        p = __fadd_rn(__fmul_rn(p, w), -4.39150654e-06f);
        p = __fadd_rn(__fmul_rn(p, w), 0.00021858087f);
        p = __fadd_rn(__fmul_rn(p, w), -0.00125372503f);
        p = __fadd_rn(__fmul_rn(p, w), -0.00417768164f);
        p = __fadd_rn(__fmul_rn(p, w), 0.246640727f);
        p = __fadd_rn(__fmul_rn(p, w), 1.50140941f);
    } else {
        w = __fadd_rn(sqrtf(w), -3.0f);
        p = -0.000200214257f;
        p = __fadd_rn(__fmul_rn(p, w), 0.000100950558f);
        p = __fadd_rn(__fmul_rn(p, w), 0.00134934322f);
        p = __fadd_rn(__fmul_rn(p, w), -0.00367342844f);
        p = __fadd_rn(__fmul_rn(p, w), 0.00573950773f);
        p = __fadd_rn(__fmul_rn(p, w), -0.0076224613f);
        p = __fadd_rn(__fmul_rn(p, w), 0.00943887047f);
        p = __fadd_rn(__fmul_rn(p, w), 1.00167406f);
        p = __fadd_rn(__fmul_rn(p, w), 2.83297682f);
    }
    return __fmul_rn(1.41421354f, __fmul_rn(p, x));
}

// ---------------- fused init kernel: one CTA per batch, 1024 threads ----------------
__global__ void __launch_bounds__(1024, 1)
init_kernel(const float* __restrict__ z, const int* __restrict__ is_input) {
    __shared__ float v0s[32];
    const int b = blockIdx.x;
    const int w = threadIdx.x >> 5;
    const int l = threadIdx.x & 31;
    unsigned k1a, k1b, k2a, k2b; derive_keys(k1a, k1b, k2a, k2b);

    if (w == 0) {
        float n = bits_to_normal(tf_bits(k1a, k1b, (unsigned)(b * 32 + l)));
        float ss = warp_sum(__fmul_rn(n, n));
        float v0 = n / sqrtf(ss);
        v0s[l] = v0;
        v0_g[b * 32 + l] = v0;
    }
    __syncthreads();
    float v0l = v0s[l];

#pragma unroll 1
    for (int k = 0; k < 32; k++) {
        int n = w * 32 + k;
        unsigned e = ((unsigned)(b * 1024 + n)) * 32u + (unsigned)l;
        float r = bits_to_normal(tf_bits(k2a, k2b, e));
        float d = warp_sum(__fmul_rn(r, v0l));
        float rp = __fadd_rn(r, -__fmul_rn(d, v0l));
        float nr = sqrtf(warp_sum(__fmul_rn(rp, rp)));
        float R = rp / nr;

        float zf; int ii;
        if (n == 0)        { zf = 1.0f; ii = 1; }
        else if (n <= NIN) { zf = z[b * NIN + n - 1]; ii = is_input[b * NIN + n - 1]; }
        else               { zf = 0.0f; ii = 0; }

        float V;
        if (ii > 0) {
            float x = __fmul_rn(PI_F, zf);
            V = __fadd_rn(__fmul_rn(-cosf(x), v0l), __fmul_rn(sinf(x), R));
        } else {
            V = R;
        }
        if (n == 0) V = v0l;
        V_g[((size_t)b * 1024 + n) * 32 + l] = V;
    }

    // free list (warp 31)
    if (w == 31) {
        int m = 0;
        for (int base = 1; base < 1024; base += 32) {
            int n = base + l;
            bool f = (n < 1024) && (n > NIN || is_input[b * NIN + n - 1] == 0);
            unsigned msk = __ballot_sync(0xffffffffu, f);
            if (f) {
                int pos = m + __popc(msk & ((1u << l) - 1u));
                list_g[b * 1024 + pos] = (unsigned short)n;
            }
            m += __popc(msk);
        }
        if (l == 0) cnt_g[b] = m;
    }
    __syncthreads();

    // VH fill: VH[b][m] = V_init[b][lst[m]]
    int c = cnt_g[b];
    for (int m = w; m < c; m += 32) {
        int i = list_g[b * 1024 + m];
        VH_g[((size_t)b * 1024 + m) * 32 + l] = V_g[((size_t)b * 1024 + i) * 32 + l];
    }
}

// ---------------- mix kernel: 2-CTA cluster, mbarrier-decoupled pipeline ----------------
// CTA0: warps 0-7 dots (rows 0..511), warp 8 reducer.
// CTA1: warps 0-7 dots (rows 512..1023), warp 8 pre-reducer.
// Dots at group k apply vn(k-3) then produce partials(k) (missing k-1,k-2 ->
// two-group exact corrections, verified). No per-phase cluster barrier.
__global__ void __launch_bounds__(288, 1) __cluster_dims__(2, 1, 1)
mix_kernel(const float* __restrict__ C,
           const float* __restrict__ z,
           const int* __restrict__ is_input,
           float* __restrict__ out) {
    extern __shared__ __align__(16) float sm[];
    unsigned short* lstS = (unsigned short*)&sm[F_LST];
    __shared__ __align__(8) unsigned long long mbPart[3];
    __shared__ __align__(8) unsigned long long mbVn[4];

    uint32_t rank;
    asm("mov.u32 %0, %%cluster_ctarank;" : "=r"(rank));
    const int b = blockIdx.x >> 1;
    const int tid = threadIdx.x;
    const int w = tid >> 5;           // 0..8
    const int l = tid & 31;
    const bool dotw = (w < 8);
    const bool redw = (rank == 0) && (w == 8);
    const bool prew = (rank == 1) && (w == 8);
    const uint32_t smb = smem_u32(sm);
    const uint32_t mbPartA = smem_u32(mbPart);
    const uint32_t mbVnA = smem_u32(mbVn);

    __shared__ int scnt;
    for (int idx = tid; idx < 1024; idx += 288)
        lstS[idx] = list_g[b * 1024 + idx];
    if (tid == 0) {
        scnt = cnt_g[b];
        mbar_init(mbPartA + 0, rank == 0 ? 288u : 256u);
        mbar_init(mbPartA + 8, rank == 0 ? 288u : 256u);
        mbar_init(mbPartA + 16, rank == 0 ? 288u : 256u);
        mbar_init(mbVnA + 0, 32u);
        mbar_init(mbVnA + 8, 32u);
        mbar_init(mbVnA + 16, 32u);
        mbar_init(mbVnA + 24, 32u);
    }
    __syncthreads();
    const int cnt = scnt;
    const int total = cnt * SWEEPS;
    const int P = (total + S - 1) / S;

    // coupling tables (CTA0 only): svd[d][m] = C[lst[(m+d+1)%cnt], lst[m]], dist 1..11
    if (rank == 0) {
        for (int t = tid; t < 11 * cnt; t += 288) {
            int d = t / cnt;
            int m = t - d * cnt;
            int mp = m + d + 1; if (mp >= cnt) mp -= cnt;
            sm[F_SVD + d * 1024 + m] =
                __ldg(C + (size_t)lstS[mp] * NVARS + lstS[m]);
        }
    }

    // V registers: CTA rank owns rows [512*rank, +512), warp w -> 64 rows
    unsigned long long v2[32];
    const int rowbase = (int)rank * 512 + w * 64;
    if (dotw) {
#pragma unroll
        for (int p = 0; p < 32; p++) {
            int row = rowbase + 2 * p;
            v2[p] = pk2(V_g[((size_t)b * 1024 + row) * 32 + l],
                        V_g[((size_t)b * 1024 + row + 1) * 32 + l]);
        }
    }

    // staging: tid<256: half-row s = tid>>6, chunks at (tid&63)*4 and +256
    const int st_s = tid >> 6;
    const int st_c = (tid & 63) * 4;

    // prologue staging: group 0 -> slot 0, group 1 -> slot 1
    if (tid < 256) {
        const float* src = C + (size_t)lstS[st_s] * NVARS + rank * 512;
        float* dst = &sm[F_CBUF + (0 * 4 + st_s) * 512];
        __pipeline_memcpy_async(dst + st_c, src + st_c, 16);
        __pipeline_memcpy_async(dst + st_c + 256, src + st_c + 256, 16);
    }
    __pipeline_commit();
    if (tid < 256) {
        int mq = (S + st_s) % cnt;
        const float* src = C + (size_t)lstS[mq] * NVARS + rank * 512;
        float* dst = &sm[F_CBUF + (1 * 4 + st_s) * 512];
        __pipeline_memcpy_async(dst + st_c, src + st_c, 16);
        __pipeline_memcpy_async(dst + st_c + 256, src + st_c + 256, 16);
    }
    __pipeline_commit();

    __syncthreads();       // svd + lst + mbarrier init visible intra-CTA
    CLUSTER_SYNC();        // mbarriers visible cluster-wide before any remote arrive

    // ================= role loops =================
    if (dotw) {
        int m_cur = 0;                   // base of group k
        int m_stage = (2 * S) % cnt;     // base of group k+2
        int m_app = 0;                   // base of group k-3 (valid from k=3)
        for (int k = 0; k < P; k++) {
            // (1) wait vn(k-3), apply inserts
            if (k >= 3) {
                int g = k - 3;
                mbar_wait(mbVnA + (g & 3) * 8, (unsigned)((g >> 2) & 1));
#pragma unroll
                for (int s = 0; s < S; s++) {
                    int mp = m_app + s; if (mp >= cnt) mp -= cnt;
                    int i = lstS[mp];
                    if ((i >> 6) == (int)rank * 8 + w)
                        insert_pred(v2, i & 63, sm[F_VNB + (g & 3) * 128 + s * 32 + l]);
                }
                m_app += S; if (m_app >= cnt) m_app -= cnt;
            }
            // (2) cbuf slot k%3 ready + cross-warp visibility
            __pipeline_wait_prior(1);
            asm volatile("bar.sync 1, 256;" ::: "memory");
            // (3) stage group k+2 into slot (k+2)%3
            {
                int mq = m_stage + st_s; if (mq >= cnt) mq -= cnt;
                const float* src = C + (size_t)lstS[mq] * NVARS + rank * 512;
                float* dst = &sm[F_CBUF + (((k + 2) % 3) * 4 + st_s) * 512];
                __pipeline_memcpy_async(dst + st_c, src + st_c, 16);
                __pipeline_memcpy_async(dst + st_c + 256, src + st_c + 256, 16);
                __pipeline_commit();
                m_stage += S; if (m_stage >= cnt) m_stage -= cnt;
            }
            // (4) dots for group k from slot k%3 -> local pT slot k%3
            int slotc = (k % 3) * 4;
            int slotp = (k % 3) * 1024;
#pragma unroll
            for (int s = 0; s < S; s++) {
                const ulonglong2* Cs = reinterpret_cast<const ulonglong2*>(
                    &sm[F_CBUF + (slotc + s) * 512 + w * 64]);
                sm[F_PT + slotp + s * 256 + w * 32 + l] = dot_row(Cs, v2);
            }
            // (5) signal partials (release orders the pT stores)
            mbar_arrive_local(mbPartA + (k % 3) * 8);
            m_cur += S; if (m_cur >= cnt) m_cur -= cnt;
        }
        // drain: apply vn(P-3), vn(P-2), vn(P-1)
        for (int g = (P >= 3 ? P - 3 : 0); g < P; g++) {
            mbar_wait(mbVnA + (g & 3) * 8, (unsigned)((g >> 2) & 1));
#pragma unroll
            for (int s = 0; s < S; s++) {
                if (g * S + s < total) {
                    int mp = m_app + s; if (mp >= cnt) mp -= cnt;
                    int i = lstS[mp];
                    if ((i >> 6) == (int)rank * 8 + w)
                        insert_pred(v2, i & 63, sm[F_VNB + (g & 3) * 128 + s * 32 + l]);
                }
            }
            m_app += S; if (m_app >= cnt) m_app -= cnt;
        }
        __pipeline_wait_prior(0);
    } else if (prew) {
        // CTA1 pre-reducer: tree-sum local partials, push 512B + arrive to CTA0
        int s3 = 0; unsigned p3v = 0;
        for (int k = 0; k < P; k++) {
            mbar_wait(mbPartA + s3 * 8, p3v);
            int slotp = s3 * 1024;
#pragma unroll
            for (int s = 0; s < S; s++) {
                const float* pr = &sm[F_PT + slotp + s * 256];
                float t0 = pr[0*32+l], t1 = pr[1*32+l], t2 = pr[2*32+l], t3 = pr[3*32+l];
                float t4 = pr[4*32+l], t5 = pr[5*32+l], t6 = pr[6*32+l], t7 = pr[7*32+l];
                float rs = ((t0 + t1) + (t2 + t3)) + ((t4 + t5) + (t6 + t7));
                sts_remote(smb + (F_RSUM + s3 * 128 + s * 32 + l) * 4, 0, rs);
            }
            mbar_arrive_remote(mbPartA + s3 * 8, 0);
            s3++; if (s3 == 3) { s3 = 0; p3v ^= 1u; }
        }
    } else if (redw) {
        // CTA0 reducer
        float dvP1[S] = {0.f, 0.f, 0.f, 0.f};
        float dvP2[S] = {0.f, 0.f, 0.f, 0.f};
        float vold_cur[S];
#pragma unroll
        for (int s = 0; s < S; s++)
            vold_cur[s] = VH_g[((size_t)b * 1024 + s) * 32 + l];

        int m_prev2 = 0, m_prev = 0, m_cur = 0, m_n1 = S % cnt;
        int s3 = 0; unsigned p3v = 0;
        for (int k = 0; k < P; k++) {
            mbar_wait(mbPartA + s3 * 8, p3v);
            // prefetch vold for group k+1
            float vold_nxt[S];
#pragma unroll
            for (int s = 0; s < S; s++) {
                int mq = m_n1 + s; if (mq >= cnt) mq -= cnt;
                vold_nxt[s] = VH_g[((size_t)b * 1024 + mq) * 32 + l];
            }
            // base: 8 local partials + remote pre-sum + two-group-back corrections
            float base[S];
            int slotp = s3 * 1024;
#pragma unroll
            for (int s = 0; s < S; s++) {
                const float* pr = &sm[F_PT + slotp + s * 256];
                float t0 = pr[0*32+l], t1 = pr[1*32+l], t2 = pr[2*32+l], t3 = pr[3*32+l];
                float t4 = pr[4*32+l], t5 = pr[5*32+l], t6 = pr[6*32+l], t7 = pr[7*32+l];
                float g = ((t0 + t1) + (t2 + t3)) + ((t4 + t5) + (t6 + t7));
                g += sm[F_RSUM + s3 * 128 + s * 32 + l];
#pragma unroll
                for (int sp = 0; sp < S; sp++) {
                    int d2 = 2 * S + s - sp;            // 5..11
                    int mq2 = m_prev2 + sp; if (mq2 >= cnt) mq2 -= cnt;
                    g = fmaf(sm[F_SVD + (d2 - 1) * 1024 + mq2], dvP2[sp], g);
                    int d1 = S + s - sp;                // 1..7
                    int mq1 = m_prev + sp; if (mq1 >= cnt) mq1 -= cnt;
                    g = fmaf(sm[F_SVD + (d1 - 1) * 1024 + mq1], dvP1[sp], g);
                }
                base[s] = g;
            }
            // serial chain: intra-group corrections + normalize
            float dv_new[S];
#pragma unroll
            for (int s = 0; s < S; s++) {
                float g = base[s];
#pragma unroll
                for (int sp = 0; sp < S; sp++)
                    if (sp < s) {
                        int d = s - sp;                 // 1..3
                        int mq = m_cur + sp; if (mq >= cnt) mq -= cnt;
                        g = fmaf(sm[F_SVD + (d - 1) * 1024 + mq], dv_new[sp], g);
                    }
                float ss = warp_sum(g * g);
                ss = fmaxf(ss, 1e-24f);
                float vn = -g * rsqrtf(ss);
                int voff = F_VNB + (k & 3) * 128 + s * 32 + l;
                sm[voff] = vn;
                sts_remote(smb + voff * 4, 1, vn);
                int mq = m_cur + s; if (mq >= cnt) mq -= cnt;
                VH_g[((size_t)b * 1024 + mq) * 32 + l] = vn;
                dv_new[s] = vn - vold_cur[s];
            }
            // publish vn(k) locally and to CTA1
            mbar_arrive_local(mbVnA + (k & 3) * 8);
            mbar_arrive_remote(mbVnA + (k & 3) * 8, 1);
#pragma unroll
            for (int s = 0; s < S; s++) {
                dvP2[s] = dvP1[s]; dvP1[s] = dv_new[s]; vold_cur[s] = vold_nxt[s];
            }
            m_prev2 = m_prev; m_prev = m_cur; m_cur = m_n1;
            m_n1 += S; if (m_n1 >= cnt) m_n1 -= cnt;
            s3++; if (s3 == 3) { s3 = 0; p3v ^= 1u; }
        }
    }

    CLUSTER_SYNC();   // all remote traffic complete before anyone exits

    // ---------------- epilogue: z_out[:, 1:769] ----------------
    if (dotw) {
        float v0l = v0_g[b * 32 + l];
        const float CLO = (float)(-1.0 + 1e-7);
        const float CHI = (float)( 1.0 - 1e-7);
#pragma unroll
        for (int j = 0; j < 64; j++) {
            int n = rowbase + j;
            if (n >= 1 && n <= NIN) {
                float x, y; up2(v2[j >> 1], x, y);
                float Vv = (j & 1) ? y : x;
                float d = warp_sum(__fmul_rn(Vv, v0l));
                if (l == 0) {
                    int idx = b * NIN + n - 1;
                    float res;
                    if (is_input[idx] != 0) {
                        res = z[idx];
                    } else {
                        float ca = fminf(fmaxf(-d, CLO), CHI);
                        res = acosf(ca) / PI_F;
                    }
                    out[idx] = res;
                }
            }
        }
    }
}

// ---------------- launcher ----------------
extern "C" void kernel_launch(void* const* d_in, const int* in_sizes, int n_in,
                              void* d_out, int out_size) {
    const float* C        = (const float*)d_in[0];
    const float* z        = (const float*)d_in[1];
    const int*   is_input = (const int*)d_in[2];
    float* out = (float*)d_out;

    cudaFuncSetAttribute(mix_kernel,
                         cudaFuncAttributeMaxDynamicSharedMemorySize, SMEM_BYTES);

    init_kernel<<<BATCH, 1024>>>(z, is_input);
    mix_kernel<<<2 * BATCH, 288, SMEM_BYTES>>>(C, z, is_input, out);
}

// round 16
// speedup vs baseline: 1.1857x; 1.0344x over previous
#include <cuda_runtime.h>
#include <cuda_pipeline.h>
#include <cstdint>
#include <math.h>

#define NVARS 1024
#define BATCH 64
#define KDIM  32
#define NIN   768
#define SWEEPS 10
#define PI_F 3.14159274101257324f
#define S 8

// dynamic smem layout (floats)
#define F_CBUF 0            // 3 groups x 8 half-rows x 512 cp.async ring (48 KB)
#define F_SVD  12288        // 23 * 1024 coupling tables, distance 1..23 (CTA0 uses)
#define F_PT   35840        // 3 * 8 * 256 local partials [slot3][s][warp8][lane]
#define F_RSUM 41984        // 3 * 8 * 32 pre-reduced CTA1 partials (on CTA0)
#define F_VNB  42752        // 4 * 8 * 32 vn broadcast (depth-4 ring)
#define F_LST  43776        // 1024 ushort = 512 floats
#define SMEM_FLOATS 44288
#define SMEM_BYTES (SMEM_FLOATS * 4)   // ~173 KB

// ---------------- persistent scratch (no runtime allocation) ----------------
__device__ float V_g[BATCH * NVARS * KDIM];     // 8 MB
__device__ float VH_g[BATCH * NVARS * KDIM];    // 8 MB value-history by list position
__device__ float v0_g[BATCH * KDIM];
__device__ unsigned short list_g[BATCH * NVARS];
__device__ int cnt_g[BATCH];

// ---------------- f32x2 helpers ----------------
__device__ __forceinline__ void ffma2(unsigned long long &d, unsigned long long a,
                                      unsigned long long b) {
    asm("fma.rn.f32x2 %0, %1, %2, %3;" : "=l"(d) : "l"(a), "l"(b), "l"(d));
}
__device__ __forceinline__ void fadd2(unsigned long long &d, unsigned long long a,
                                      unsigned long long b) {
    asm("add.rn.f32x2 %0, %1, %2;" : "=l"(d) : "l"(a), "l"(b));
}
__device__ __forceinline__ unsigned long long pk2(float lo, float hi) {
    unsigned long long r;
    asm("mov.b64 %0, {%1, %2};" : "=l"(r) : "f"(lo), "f"(hi));
    return r;
}
__device__ __forceinline__ void up2(unsigned long long v, float &lo, float &hi) {
    asm("mov.b64 {%0, %1}, %2;" : "=f"(lo), "=f"(hi) : "l"(v));
}

__device__ __forceinline__ float warp_sum(float v) {
#pragma unroll
    for (int off = 16; off; off >>= 1)
        v += __shfl_xor_sync(0xffffffffu, v, off);
    return v;
}

__device__ __forceinline__ uint32_t smem_u32(const void* p) {
    uint32_t a;
    asm("{ .reg .u64 t; cvta.to.shared.u64 t, %1; cvt.u32.u64 %0, t; }"
        : "=r"(a) : "l"(p));
    return a;
}

// store one f32 into the peer CTA's smem at the same offset
__device__ __forceinline__ void sts_remote(uint32_t laddr, uint32_t trank, float v) {
    uint32_t raddr;
    asm("mapa.shared::cluster.u32 %0, %1, %2;" : "=r"(raddr) : "r"(laddr), "r"(trank));
    asm volatile("st.shared::cluster.b32 [%0], %1;"
                 :: "r"(raddr), "r"(__float_as_uint(v)) : "memory");
}

// ---- mbarrier helpers ----
__device__ __forceinline__ void mbar_init(uint32_t addr, uint32_t count) {
    asm volatile("mbarrier.init.shared.b64 [%0], %1;" :: "r"(addr), "r"(count) : "memory");
}
__device__ __forceinline__ void mbar_arrive_local(uint32_t addr) {
    asm volatile("mbarrier.arrive.release.cta.shared::cta.b64 _, [%0];"
                 :: "r"(addr) : "memory");
}
__device__ __forceinline__ void mbar_arrive_remote(uint32_t laddr, uint32_t trank) {
    uint32_t raddr;
    asm("mapa.shared::cluster.u32 %0, %1, %2;" : "=r"(raddr) : "r"(laddr), "r"(trank));
    asm volatile("mbarrier.arrive.release.cluster.shared::cluster.b64 _, [%0];"
                 :: "r"(raddr) : "memory");
}
__device__ __forceinline__ void mbar_wait(uint32_t addr, uint32_t parity) {
    uint32_t done;
    asm volatile(
        "{\n\t.reg .pred p;\n\t"
        "mbarrier.try_wait.parity.acquire.cluster.shared::cta.b64 p, [%1], %2;\n\t"
        "selp.b32 %0, 1, 0, p;\n\t}"
        : "=r"(done) : "r"(addr), "r"(parity) : "memory");
    if (!done) {
        asm volatile(
            "{\n\t.reg .pred P1;\n\t"
            "WL_%=:\n\t"
            "mbarrier.try_wait.parity.acquire.cluster.shared::cta.b64 P1, [%0], %1, 0x989680;\n\t"
            "@P1 bra.uni WD_%=;\n\t"
            "bra.uni WL_%=;\n\t"
            "WD_%=:\n\t}"
            :: "r"(addr), "r"(parity) : "memory");
    }
}

#define CLUSTER_SYNC() do { \
    asm volatile("barrier.cluster.arrive.aligned;" ::: "memory"); \
    asm volatile("barrier.cluster.wait.aligned;" ::: "memory"); \
} while (0)

// half-row dot: 64 floats (16 ulonglong2) against v2[32]
__device__ __forceinline__ float dot_row(const ulonglong2* __restrict__ Cp,
                                         const unsigned long long (&v2)[32]) {
    unsigned long long a0 = 0ull, a1 = 0ull, a2 = 0ull, a3 = 0ull;
#pragma unroll
    for (int q = 0; q < 16; q++) {
        ulonglong2 cc = Cp[q];
        ffma2(((q & 1) ? a2 : a0), cc.x, v2[2 * q]);
        ffma2(((q & 1) ? a3 : a1), cc.y, v2[2 * q + 1]);
    }
    fadd2(a0, a0, a2); fadd2(a1, a1, a3); fadd2(a0, a0, a1);
    float x, y; up2(a0, x, y);
    return x + y;
}

// predicated-chain insert (verified form)
__device__ __forceinline__ void insert_pred(unsigned long long (&v2)[32], int j, float vn) {
    int p0 = j >> 1;
#pragma unroll
    for (int p = 0; p < 32; p++)
        if (p == p0) {
            float x, y; up2(v2[p], x, y);
            if (j & 1) y = vn; else x = vn;
            v2[p] = pk2(x, y);
        }
}

// ---------------- threefry2x32 core, exact JAX schedule ----------------
__device__ __forceinline__ void tf2x32(unsigned k0, unsigned k1,
                                       unsigned x0, unsigned x1,
                                       unsigned &y0, unsigned &y1) {
    unsigned ks2 = k0 ^ k1 ^ 0x1BD11BDAu;
    x0 += k0; x1 += k1;
#define TFR(r) { x0 += x1; x1 = (x1 << r) | (x1 >> (32 - r)); x1 ^= x0; }
    TFR(13) TFR(15) TFR(26) TFR(6)  x0 += k1;  x1 += ks2 + 1u;
    TFR(17) TFR(29) TFR(16) TFR(24) x0 += ks2; x1 += k0 + 2u;
    TFR(13) TFR(15) TFR(26) TFR(6)  x0 += k0;  x1 += k1 + 3u;
    TFR(17) TFR(29) TFR(16) TFR(24) x0 += k1;  x1 += ks2 + 4u;
    TFR(13) TFR(15) TFR(26) TFR(6)  x0 += ks2; x1 += k0 + 5u;
#undef TFR
    y0 = x0; y1 = x1;
}

// PARTITIONABLE threefry (modern JAX default)
__device__ __forceinline__ void derive_keys(unsigned &k1a, unsigned &k1b,
                                            unsigned &k2a, unsigned &k2b) {
    tf2x32(0u, 42u, 0u, 0u, k1a, k1b);
    tf2x32(0u, 42u, 0u, 1u, k2a, k2b);
}

__device__ __forceinline__ unsigned tf_bits(unsigned ka, unsigned kb, unsigned e) {
    unsigned y0, y1;
    tf2x32(ka, kb, 0u, e, y0, y1);
    return y0 ^ y1;
}

__device__ __forceinline__ float bits_to_normal(unsigned bits) {
    float u01 = __fadd_rn(__uint_as_float((bits >> 9) | 0x3F800000u), -1.0f);
    float u = __fadd_rn(__fmul_rn(u01, 2.0f), -0.99999994f);
    u = fmaxf(u, -0.99999994f);
    float x = u;
    float xx = __fmul_rn(x, x);
    float w = -log1pf(-xx);
    float p;
    if (w < 5.0f) {
        w = __fadd_rn(w, -2.5f);
        p = 2.81022636e-08f;
        p = __fadd_rn(__fmul_rn(p, w), 3.43273939e-07f);
        p = __fadd_rn(__fmul_rn(p, w), -3.5233877e-06f);
        p = __fadd_rn(__fmul_rn(p, w), -4.39150654e-06f);
        p = __fadd_rn(__fmul_rn(p, w), 0.00021858087f);
        p = __fadd_rn(__fmul_rn(p, w), -0.00125372503f);
        p = __fadd_rn(__fmul_rn(p, w), -0.00417768164f);
        p = __fadd_rn(__fmul_rn(p, w), 0.246640727f);
        p = __fadd_rn(__fmul_rn(p, w), 1.50140941f);
    } else {
        w = __fadd_rn(sqrtf(w), -3.0f);
        p = -0.000200214257f;
        p = __fadd_rn(__fmul_rn(p, w), 0.000100950558f);
        p = __fadd_rn(__fmul_rn(p, w), 0.00134934322f);
        p = __fadd_rn(__fmul_rn(p, w), -0.00367342844f);
        p = __fadd_rn(__fmul_rn(p, w), 0.00573950773f);
        p = __fadd_rn(__fmul_rn(p, w), -0.0076224613f);
        p = __fadd_rn(__fmul_rn(p, w), 0.00943887047f);
        p = __fadd_rn(__fmul_rn(p, w), 1.00167406f);
        p = __fadd_rn(__fmul_rn(p, w), 2.83297682f);
    }
    return __fmul_rn(1.41421354f, __fmul_rn(p, x));
}

// ---------------- fused init kernel: one CTA per batch, 1024 threads ----------------
__global__ void __launch_bounds__(1024, 1)
init_kernel(const float* __restrict__ z, const int* __restrict__ is_input) {
    __shared__ float v0s[32];
    const int b = blockIdx.x;
    const int w = threadIdx.x >> 5;
    const int l = threadIdx.x & 31;
    unsigned k1a, k1b, k2a, k2b; derive_keys(k1a, k1b, k2a, k2b);

    if (w == 0) {
        float n = bits_to_normal(tf_bits(k1a, k1b, (unsigned)(b * 32 + l)));
        float ss = warp_sum(__fmul_rn(n, n));
        float v0 = n / sqrtf(ss);
        v0s[l] = v0;
        v0_g[b * 32 + l] = v0;
    }
    __syncthreads();
    float v0l = v0s[l];

#pragma unroll 1
    for (int k = 0; k < 32; k++) {
        int n = w * 32 + k;
        unsigned e = ((unsigned)(b * 1024 + n)) * 32u + (unsigned)l;
        float r = bits_to_normal(tf_bits(k2a, k2b, e));
        float d = warp_sum(__fmul_rn(r, v0l));
        float rp = __fadd_rn(r, -__fmul_rn(d, v0l));
        float nr = sqrtf(warp_sum(__fmul_rn(rp, rp)));
        float R = rp / nr;

        float zf; int ii;
        if (n == 0)        { zf = 1.0f; ii = 1; }
        else if (n <= NIN) { zf = z[b * NIN + n - 1]; ii = is_input[b * NIN + n - 1]; }
        else               { zf = 0.0f; ii = 0; }

        float V;
        if (ii > 0) {
            float x = __fmul_rn(PI_F, zf);
            V = __fadd_rn(__fmul_rn(-cosf(x), v0l), __fmul_rn(sinf(x), R));
        } else {
            V = R;
        }
        if (n == 0) V = v0l;
        V_g[((size_t)b * 1024 + n) * 32 + l] = V;
    }

    // free list (warp 31)
    if (w == 31) {
        int m = 0;
        for (int base = 1; base < 1024; base += 32) {
            int n = base + l;
            bool f = (n < 1024) && (n > NIN || is_input[b * NIN + n - 1] == 0);
            unsigned msk = __ballot_sync(0xffffffffu, f);
            if (f) {
                int pos = m + __popc(msk & ((1u << l) - 1u));
                list_g[b * 1024 + pos] = (unsigned short)n;
            }
            m += __popc(msk);
        }
        if (l == 0) cnt_g[b] = m;
    }
    __syncthreads();

    // VH fill: VH[b][m] = V_init[b][lst[m]]
    int c = cnt_g[b];
    for (int m = w; m < c; m += 32) {
        int i = list_g[b * 1024 + m];
        VH_g[((size_t)b * 1024 + m) * 32 + l] = V_g[((size_t)b * 1024 + i) * 32 + l];
    }
}

// ---------------- mix kernel: 2-CTA cluster, S=8, mbarrier-decoupled ----------------
// CTA0: warps 0-7 dots (rows 0..511), warp 8 reducer.
// CTA1: warps 0-7 dots (rows 512..1023), warp 8 pre-reducer.
// Dots at group k apply vn(k-3) then produce partials(k) (missing groups
// k-1, k-2 -> two-group exact corrections, distances 1..23).
__global__ void __launch_bounds__(288, 1) __cluster_dims__(2, 1, 1)
mix_kernel(const float* __restrict__ C,
           const float* __restrict__ z,
           const int* __restrict__ is_input,
           float* __restrict__ out) {
    extern __shared__ __align__(16) float sm[];
    unsigned short* lstS = (unsigned short*)&sm[F_LST];
    __shared__ __align__(8) unsigned long long mbPart[3];
    __shared__ __align__(8) unsigned long long mbVn[4];

    uint32_t rank;
    asm("mov.u32 %0, %%cluster_ctarank;" : "=r"(rank));
    const int b = blockIdx.x >> 1;
    const int tid = threadIdx.x;
    const int w = tid >> 5;           // 0..8
    const int l = tid & 31;
    const bool dotw = (w < 8);
    const bool redw = (rank == 0) && (w == 8);
    const bool prew = (rank == 1) && (w == 8);
    const uint32_t smb = smem_u32(sm);
    const uint32_t mbPartA = smem_u32(mbPart);
    const uint32_t mbVnA = smem_u32(mbVn);

    __shared__ int scnt;
    for (int idx = tid; idx < 1024; idx += 288)
        lstS[idx] = list_g[b * 1024 + idx];
    if (tid == 0) {
        scnt = cnt_g[b];
        mbar_init(mbPartA + 0, rank == 0 ? 288u : 256u);
        mbar_init(mbPartA + 8, rank == 0 ? 288u : 256u);
        mbar_init(mbPartA + 16, rank == 0 ? 288u : 256u);
        mbar_init(mbVnA + 0, 32u);
        mbar_init(mbVnA + 8, 32u);
        mbar_init(mbVnA + 16, 32u);
        mbar_init(mbVnA + 24, 32u);
    }
    __syncthreads();
    const int cnt = scnt;
    const int total = cnt * SWEEPS;
    const int P = (total + S - 1) / S;

    // coupling tables (CTA0 only): svd[d][m] = C[lst[(m+d+1)%cnt], lst[m]], dist 1..23
    if (rank == 0) {
        for (int t = tid; t < 23 * cnt; t += 288) {
            int d = t / cnt;
            int m = t - d * cnt;
            int mp = m + d + 1; if (mp >= cnt) mp -= cnt;
            sm[F_SVD + d * 1024 + m] =
                __ldg(C + (size_t)lstS[mp] * NVARS + lstS[m]);
        }
    }

    // V registers: CTA rank owns rows [512*rank, +512), warp w -> 64 rows
    unsigned long long v2[32];
    const int rowbase = (int)rank * 512 + w * 64;
    if (dotw) {
#pragma unroll
        for (int p = 0; p < 32; p++) {
            int row = rowbase + 2 * p;
            v2[p] = pk2(V_g[((size_t)b * 1024 + row) * 32 + l],
                        V_g[((size_t)b * 1024 + row + 1) * 32 + l]);
        }
    }

    // staging: tid<256: half-row s = tid>>5 (0..7), 4 chunks of 16B at
    // float offsets (tid&31)*4 + {0,128,256,384}
    const int st_s = tid >> 5;
    const int st_c = (tid & 31) * 4;

    // prologue staging: group 0 -> slot 0, group 1 -> slot 1
    if (tid < 256) {
        const float* src = C + (size_t)lstS[st_s] * NVARS + rank * 512;
        float* dst = &sm[F_CBUF + (0 * 8 + st_s) * 512];
#pragma unroll
        for (int c4 = 0; c4 < 4; c4++)
            __pipeline_memcpy_async(dst + st_c + c4 * 128, src + st_c + c4 * 128, 16);
    }
    __pipeline_commit();
    if (tid < 256) {
        int mq = (S + st_s) % cnt;
        const float* src = C + (size_t)lstS[mq] * NVARS + rank * 512;
        float* dst = &sm[F_CBUF + (1 * 8 + st_s) * 512];
#pragma unroll
        for (int c4 = 0; c4 < 4; c4++)
            __pipeline_memcpy_async(dst + st_c + c4 * 128, src + st_c + c4 * 128, 16);
    }
    __pipeline_commit();

    __syncthreads();       // svd + lst + mbarrier init visible intra-CTA
    CLUSTER_SYNC();        // mbarriers visible cluster-wide before any remote arrive

    // ================= role loops =================
    if (dotw) {
        int m_stage = (2 * S) % cnt;     // base of group k+2
        int m_app = 0;                   // base of group k-3 (valid from k=3)
        for (int k = 0; k < P; k++) {
            // (1) wait vn(k-3), apply inserts
            if (k >= 3) {
                int g = k - 3;
                mbar_wait(mbVnA + (g & 3) * 8, (unsigned)((g >> 2) & 1));
#pragma unroll
                for (int s = 0; s < S; s++) {
                    int mp = m_app + s; if (mp >= cnt) mp -= cnt;
                    int i = lstS[mp];
                    if ((i >> 6) == (int)rank * 8 + w)
                        insert_pred(v2, i & 63, sm[F_VNB + (g & 3) * 256 + s * 32 + l]);
                }
                m_app += S; if (m_app >= cnt) m_app -= cnt;
            }
            // (2) cbuf slot k%3 ready + cross-warp visibility
            __pipeline_wait_prior(1);
            asm volatile("bar.sync 1, 256;" ::: "memory");
            // (3) stage group k+2 into slot (k+2)%3
            {
                int mq = m_stage + st_s; if (mq >= cnt) mq -= cnt;
                const float* src = C + (size_t)lstS[mq] * NVARS + rank * 512;
                float* dst = &sm[F_CBUF + (((k + 2) % 3) * 8 + st_s) * 512];
#pragma unroll
                for (int c4 = 0; c4 < 4; c4++)
                    __pipeline_memcpy_async(dst + st_c + c4 * 128, src + st_c + c4 * 128, 16);
                __pipeline_commit();
                m_stage += S; if (m_stage >= cnt) m_stage -= cnt;
            }
            // (4) dots for group k from slot k%3 -> local pT slot k%3
            int slotc = (k % 3) * 8;
            int slotp = (k % 3) * 2048;
#pragma unroll
            for (int s = 0; s < S; s++) {
                const ulonglong2* Cs = reinterpret_cast<const ulonglong2*>(
                    &sm[F_CBUF + (slotc + s) * 512 + w * 64]);
                sm[F_PT + slotp + s * 256 + w * 32 + l] = dot_row(Cs, v2);
            }
            // (5) signal partials (release orders the pT stores)
            mbar_arrive_local(mbPartA + (k % 3) * 8);
        }
        // drain: apply vn(P-3), vn(P-2), vn(P-1)
        for (int g = (P >= 3 ? P - 3 : 0); g < P; g++) {
            mbar_wait(mbVnA + (g & 3) * 8, (unsigned)((g >> 2) & 1));
#pragma unroll
            for (int s = 0; s < S; s++) {
                if (g * S + s < total) {
                    int mp = m_app + s; if (mp >= cnt) mp -= cnt;
                    int i = lstS[mp];
                    if ((i >> 6) == (int)rank * 8 + w)
                        insert_pred(v2, i & 63, sm[F_VNB + (g & 3) * 256 + s * 32 + l]);
                }
            }
            m_app += S; if (m_app >= cnt) m_app -= cnt;
        }
        __pipeline_wait_prior(0);
    } else if (prew) {
        // CTA1 pre-reducer: tree-sum local partials, push 1KB + arrive to CTA0
        int s3 = 0; unsigned p3v = 0;
        for (int k = 0; k < P; k++) {
            mbar_wait(mbPartA + s3 * 8, p3v);
            int slotp = s3 * 2048;
#pragma unroll
            for (int s = 0; s < S; s++) {
                const float* pr = &sm[F_PT + slotp + s * 256];
                float t0 = pr[0*32+l], t1 = pr[1*32+l], t2 = pr[2*32+l], t3 = pr[3*32+l];
                float t4 = pr[4*32+l], t5 = pr[5*32+l], t6 = pr[6*32+l], t7 = pr[7*32+l];
                float rs = ((t0 + t1) + (t2 + t3)) + ((t4 + t5) + (t6 + t7));
                sts_remote(smb + (F_RSUM + s3 * 256 + s * 32 + l) * 4, 0, rs);
            }
            mbar_arrive_remote(mbPartA + s3 * 8, 0);
            s3++; if (s3 == 3) { s3 = 0; p3v ^= 1u; }
        }
    } else if (redw) {
        // CTA0 reducer
        float dvP1[S], dvP2[S], vold_cur[S];
#pragma unroll
        for (int s = 0; s < S; s++) {
            dvP1[s] = 0.f; dvP2[s] = 0.f;
            vold_cur[s] = VH_g[((size_t)b * 1024 + s) * 32 + l];
        }

        int m_prev2 = 0, m_prev = 0, m_cur = 0, m_n1 = S % cnt;
        int s3 = 0; unsigned p3v = 0;
        for (int k = 0; k < P; k++) {
            mbar_wait(mbPartA + s3 * 8, p3v);
            // prefetch vold for group k+1
            float vold_nxt[S];
#pragma unroll
            for (int s = 0; s < S; s++) {
                int mq = m_n1 + s; if (mq >= cnt) mq -= cnt;
                vold_nxt[s] = VH_g[((size_t)b * 1024 + mq) * 32 + l];
            }
            // base: 8 local partials + remote pre-sum + two-group-back corrections
            float base[S];
            int slotp = s3 * 2048;
#pragma unroll
            for (int s = 0; s < S; s++) {
                const float* pr = &sm[F_PT + slotp + s * 256];
                float t0 = pr[0*32+l], t1 = pr[1*32+l], t2 = pr[2*32+l], t3 = pr[3*32+l];
                float t4 = pr[4*32+l], t5 = pr[5*32+l], t6 = pr[6*32+l], t7 = pr[7*32+l];
                float g = ((t0 + t1) + (t2 + t3)) + ((t4 + t5) + (t6 + t7));
                g += sm[F_RSUM + s3 * 256 + s * 32 + l];
#pragma unroll
                for (int sp = 0; sp < S; sp++) {
                    int d2 = 2 * S + s - sp;            // 9..23
                    int mq2 = m_prev2 + sp; if (mq2 >= cnt) mq2 -= cnt;
                    g = fmaf(sm[F_SVD + (d2 - 1) * 1024 + mq2], dvP2[sp], g);
                    int d1 = S + s - sp;                // 1..15
                    int mq1 = m_prev + sp; if (mq1 >= cnt) mq1 -= cnt;
                    g = fmaf(sm[F_SVD + (d1 - 1) * 1024 + mq1], dvP1[sp], g);
                }
                base[s] = g;
            }
            // serial chain: intra-group corrections + normalize
            float dv_new[S];
#pragma unroll
            for (int s = 0; s < S; s++) {
                float g = base[s];
#pragma unroll
                for (int sp = 0; sp < S; sp++)
                    if (sp < s) {
                        int d = s - sp;                 // 1..7
                        int mq = m_cur + sp; if (mq >= cnt) mq -= cnt;
                        g = fmaf(sm[F_SVD + (d - 1) * 1024 + mq], dv_new[sp], g);
                    }
                float ss = warp_sum(g * g);
                ss = fmaxf(ss, 1e-24f);
                float vn = -g * rsqrtf(ss);
                int voff = F_VNB + (k & 3) * 256 + s * 32 + l;
                sm[voff] = vn;
                sts_remote(smb + voff * 4, 1, vn);
                int mq = m_cur + s; if (mq >= cnt) mq -= cnt;
                VH_g[((size_t)b * 1024 + mq) * 32 + l] = vn;
                dv_new[s] = vn - vold_cur[s];
            }
            // publish vn(k) locally and to CTA1
            mbar_arrive_local(mbVnA + (k & 3) * 8);
            mbar_arrive_remote(mbVnA + (k & 3) * 8, 1);
#pragma unroll
            for (int s = 0; s < S; s++) {
                dvP2[s] = dvP1[s]; dvP1[s] = dv_new[s]; vold_cur[s] = vold_nxt[s];
            }
            m_prev2 = m_prev; m_prev = m_cur; m_cur = m_n1;
            m_n1 += S; if (m_n1 >= cnt) m_n1 -= cnt;
            s3++; if (s3 == 3) { s3 = 0; p3v ^= 1u; }
        }
    }

    CLUSTER_SYNC();   // all remote traffic complete before anyone exits

    // ---------------- epilogue: z_out[:, 1:769] ----------------
    if (dotw) {
        float v0l = v0_g[b * 32 + l];
        const float CLO = (float)(-1.0 + 1e-7);
        const float CHI = (float)( 1.0 - 1e-7);
#pragma unroll
        for (int j = 0; j < 64; j++) {
            int n = rowbase + j;
            if (n >= 1 && n <= NIN) {
                float x, y; up2(v2[j >> 1], x, y);
                float Vv = (j & 1) ? y : x;
                float d = warp_sum(__fmul_rn(Vv, v0l));
                if (l == 0) {
                    int idx = b * NIN + n - 1;
                    float res;
                    if (is_input[idx] != 0) {
                        res = z[idx];
                    } else {
                        float ca = fminf(fmaxf(-d, CLO), CHI);
                        res = acosf(ca) / PI_F;
                    }
                    out[idx] = res;
                }
            }
        }
    }
}

// ---------------- launcher ----------------
extern "C" void kernel_launch(void* const* d_in, const int* in_sizes, int n_in,
                              void* d_out, int out_size) {
    const float* C        = (const float*)d_in[0];
    const float* z        = (const float*)d_in[1];
    const int*   is_input = (const int*)d_in[2];
    float* out = (float*)d_out;

    cudaFuncSetAttribute(mix_kernel,
                         cudaFuncAttributeMaxDynamicSharedMemorySize, SMEM_BYTES);

    init_kernel<<<BATCH, 1024>>>(z, is_input);
    mix_kernel<<<2 * BATCH, 288, SMEM_BYTES>>>(C, z, is_input, out);
}

// round 17
// speedup vs baseline: 1.2669x; 1.0685x over previous
#include <cuda_runtime.h>
#include <cuda_pipeline.h>
#include <cstdint>
#include <math.h>

#define NVARS 1024
#define BATCH 64
#define KDIM  32
#define NIN   768
#define SWEEPS 10
#define PI_F 3.14159274101257324f
#define S 8

// dynamic smem layout (floats)
#define F_CBUF 0            // 3 groups x 8 half-rows x 512 cp.async ring (48 KB)
#define F_SVD  12288        // 23 * 1024 coupling tables, distance 1..23 (CTA0 uses)
#define F_PT   35840        // 3 * 8 * 256 local partials [slot3][s][warp8][lane]
#define F_RSUM 41984        // 3 * 8 * 32 pre-reduced CTA1 partials (on CTA0)
#define F_VNB  42752        // 4 * 8 * 32 vn broadcast (depth-4 ring)
#define F_DVB  43776        // 4 * 8 * 32 dv ring (reducer -> helper)
#define F_BASE 44800        // 2 * 8 * 32 base buffer (helper -> reducer)
#define F_LST  45312        // 1024 ushort = 512 floats
#define SMEM_FLOATS 45824
#define SMEM_BYTES (SMEM_FLOATS * 4)   // ~179 KB

// ---------------- persistent scratch (no runtime allocation) ----------------
__device__ float V_g[BATCH * NVARS * KDIM];     // 8 MB
__device__ float VH_g[BATCH * NVARS * KDIM];    // 8 MB value-history by list position
__device__ float v0_g[BATCH * KDIM];
__device__ unsigned short list_g[BATCH * NVARS];
__device__ int cnt_g[BATCH];

// ---------------- f32x2 helpers ----------------
__device__ __forceinline__ void ffma2(unsigned long long &d, unsigned long long a,
                                      unsigned long long b) {
    asm("fma.rn.f32x2 %0, %1, %2, %3;" : "=l"(d) : "l"(a), "l"(b), "l"(d));
}
__device__ __forceinline__ void fadd2(unsigned long long &d, unsigned long long a,
                                      unsigned long long b) {
    asm("add.rn.f32x2 %0, %1, %2;" : "=l"(d) : "l"(a), "l"(b));
}
__device__ __forceinline__ unsigned long long pk2(float lo, float hi) {
    unsigned long long r;
    asm("mov.b64 %0, {%1, %2};" : "=l"(r) : "f"(lo), "f"(hi));
    return r;
}
__device__ __forceinline__ void up2(unsigned long long v, float &lo, float &hi) {
    asm("mov.b64 {%0, %1}, %2;" : "=f"(lo), "=f"(hi) : "l"(v));
}

__device__ __forceinline__ float warp_sum(float v) {
#pragma unroll
    for (int off = 16; off; off >>= 1)
        v += __shfl_xor_sync(0xffffffffu, v, off);
    return v;
}

__device__ __forceinline__ uint32_t smem_u32(const void* p) {
    uint32_t a;
    asm("{ .reg .u64 t; cvta.to.shared.u64 t, %1; cvt.u32.u64 %0, t; }"
        : "=r"(a) : "l"(p));
    return a;
}

__device__ __forceinline__ void sts_remote(uint32_t laddr, uint32_t trank, float v) {
    uint32_t raddr;
    asm("mapa.shared::cluster.u32 %0, %1, %2;" : "=r"(raddr) : "r"(laddr), "r"(trank));
    asm volatile("st.shared::cluster.b32 [%0], %1;"
                 :: "r"(raddr), "r"(__float_as_uint(v)) : "memory");
}

// ---- mbarrier helpers ----
__device__ __forceinline__ void mbar_init(uint32_t addr, uint32_t count) {
    asm volatile("mbarrier.init.shared.b64 [%0], %1;" :: "r"(addr), "r"(count) : "memory");
}
__device__ __forceinline__ void mbar_arrive_local(uint32_t addr) {
    asm volatile("mbarrier.arrive.release.cta.shared::cta.b64 _, [%0];"
                 :: "r"(addr) : "memory");
}
__device__ __forceinline__ void mbar_arrive_remote(uint32_t laddr, uint32_t trank) {
    uint32_t raddr;
    asm("mapa.shared::cluster.u32 %0, %1, %2;" : "=r"(raddr) : "r"(laddr), "r"(trank));
    asm volatile("mbarrier.arrive.release.cluster.shared::cluster.b64 _, [%0];"
                 :: "r"(raddr) : "memory");
}
__device__ __forceinline__ void mbar_wait(uint32_t addr, uint32_t parity) {
    uint32_t done;
    asm volatile(
        "{\n\t.reg .pred p;\n\t"
        "mbarrier.try_wait.parity.acquire.cluster.shared::cta.b64 p, [%1], %2;\n\t"
        "selp.b32 %0, 1, 0, p;\n\t}"
        : "=r"(done) : "r"(addr), "r"(parity) : "memory");
    if (!done) {
        asm volatile(
            "{\n\t.reg .pred P1;\n\t"
            "WL_%=:\n\t"
            "mbarrier.try_wait.parity.acquire.cluster.shared::cta.b64 P1, [%0], %1, 0x989680;\n\t"
            "@P1 bra.uni WD_%=;\n\t"
            "bra.uni WL_%=;\n\t"
            "WD_%=:\n\t}"
            :: "r"(addr), "r"(parity) : "memory");
    }
}

#define CLUSTER_SYNC() do { \
    asm volatile("barrier.cluster.arrive.aligned;" ::: "memory"); \
    asm volatile("barrier.cluster.wait.aligned;" ::: "memory"); \
} while (0)

// half-row dot: 64 floats (16 ulonglong2) against v2[32]
__device__ __forceinline__ float dot_row(const ulonglong2* __restrict__ Cp,
                                         const unsigned long long (&v2)[32]) {
    unsigned long long a0 = 0ull, a1 = 0ull, a2 = 0ull, a3 = 0ull;
#pragma unroll
    for (int q = 0; q < 16; q++) {
        ulonglong2 cc = Cp[q];
        ffma2(((q & 1) ? a2 : a0), cc.x, v2[2 * q]);
        ffma2(((q & 1) ? a3 : a1), cc.y, v2[2 * q + 1]);
    }
    fadd2(a0, a0, a2); fadd2(a1, a1, a3); fadd2(a0, a0, a1);
    float x, y; up2(a0, x, y);
    return x + y;
}

// predicated-chain insert (verified form)
__device__ __forceinline__ void insert_pred(unsigned long long (&v2)[32], int j, float vn) {
    int p0 = j >> 1;
#pragma unroll
    for (int p = 0; p < 32; p++)
        if (p == p0) {
            float x, y; up2(v2[p], x, y);
            if (j & 1) y = vn; else x = vn;
            v2[p] = pk2(x, y);
        }
}

// ---------------- threefry2x32 core, exact JAX schedule ----------------
__device__ __forceinline__ void tf2x32(unsigned k0, unsigned k1,
                                       unsigned x0, unsigned x1,
                                       unsigned &y0, unsigned &y1) {
    unsigned ks2 = k0 ^ k1 ^ 0x1BD11BDAu;
    x0 += k0; x1 += k1;
#define TFR(r) { x0 += x1; x1 = (x1 << r) | (x1 >> (32 - r)); x1 ^= x0; }
    TFR(13) TFR(15) TFR(26) TFR(6)  x0 += k1;  x1 += ks2 + 1u;
    TFR(17) TFR(29) TFR(16) TFR(24) x0 += ks2; x1 += k0 + 2u;
    TFR(13) TFR(15) TFR(26) TFR(6)  x0 += k0;  x1 += k1 + 3u;
    TFR(17) TFR(29) TFR(16) TFR(24) x0 += k1;  x1 += ks2 + 4u;
    TFR(13) TFR(15) TFR(26) TFR(6)  x0 += ks2; x1 += k0 + 5u;
#undef TFR
    y0 = x0; y1 = x1;
}

// PARTITIONABLE threefry (modern JAX default)
__device__ __forceinline__ void derive_keys(unsigned &k1a, unsigned &k1b,
                                            unsigned &k2a, unsigned &k2b) {
    tf2x32(0u, 42u, 0u, 0u, k1a, k1b);
    tf2x32(0u, 42u, 0u, 1u, k2a, k2b);
}

__device__ __forceinline__ unsigned tf_bits(unsigned ka, unsigned kb, unsigned e) {
    unsigned y0, y1;
    tf2x32(ka, kb, 0u, e, y0, y1);
    return y0 ^ y1;
}

__device__ __forceinline__ float bits_to_normal(unsigned bits) {
    float u01 = __fadd_rn(__uint_as_float((bits >> 9) | 0x3F800000u), -1.0f);
    float u = __fadd_rn(__fmul_rn(u01, 2.0f), -0.99999994f);
    u = fmaxf(u, -0.99999994f);
    float x = u;
    float xx = __fmul_rn(x, x);
    float w = -log1pf(-xx);
    float p;
    if (w < 5.0f) {
        w = __fadd_rn(w, -2.5f);
        p = 2.81022636e-08f;
        p = __fadd_rn(__fmul_rn(p, w), 3.43273939e-07f);
        p = __fadd_rn(__fmul_rn(p, w), -3.5233877e-06f);
        p = __fadd_rn(__fmul_rn(p, w), -4.39150654e-06f);
        p = __fadd_rn(__fmul_rn(p, w), 0.00021858087f);
        p = __fadd_rn(__fmul_rn(p, w), -0.00125372503f);
        p = __fadd_rn(__fmul_rn(p, w), -0.00417768164f);
        p = __fadd_rn(__fmul_rn(p, w), 0.246640727f);
        p = __fadd_rn(__fmul_rn(p, w), 1.50140941f);
    } else {
        w = __fadd_rn(sqrtf(w), -3.0f);
        p = -0.000200214257f;
        p = __fadd_rn(__fmul_rn(p, w), 0.000100950558f);
        p = __fadd_rn(__fmul_rn(p, w), 0.00134934322f);
        p = __fadd_rn(__fmul_rn(p, w), -0.00367342844f);
        p = __fadd_rn(__fmul_rn(p, w), 0.00573950773f);
        p = __fadd_rn(__fmul_rn(p, w), -0.0076224613f);
        p = __fadd_rn(__fmul_rn(p, w), 0.00943887047f);
        p = __fadd_rn(__fmul_rn(p, w), 1.00167406f);
        p = __fadd_rn(__fmul_rn(p, w), 2.83297682f);
    }
    return __fmul_rn(1.41421354f, __fmul_rn(p, x));
}

// ---------------- fused init kernel: one CTA per batch, 1024 threads ----------------
__global__ void __launch_bounds__(1024, 1)
init_kernel(const float* __restrict__ z, const int* __restrict__ is_input) {
    __shared__ float v0s[32];
    const int b = blockIdx.x;
    const int w = threadIdx.x >> 5;
    const int l = threadIdx.x & 31;
    unsigned k1a, k1b, k2a, k2b; derive_keys(k1a, k1b, k2a, k2b);

    if (w == 0) {
        float n = bits_to_normal(tf_bits(k1a, k1b, (unsigned)(b * 32 + l)));
        float ss = warp_sum(__fmul_rn(n, n));
        float v0 = n / sqrtf(ss);
        v0s[l] = v0;
        v0_g[b * 32 + l] = v0;
    }
    __syncthreads();
    float v0l = v0s[l];

#pragma unroll 1
    for (int k = 0; k < 32; k++) {
        int n = w * 32 + k;
        unsigned e = ((unsigned)(b * 1024 + n)) * 32u + (unsigned)l;
        float r = bits_to_normal(tf_bits(k2a, k2b, e));
        float d = warp_sum(__fmul_rn(r, v0l));
        float rp = __fadd_rn(r, -__fmul_rn(d, v0l));
        float nr = sqrtf(warp_sum(__fmul_rn(rp, rp)));
        float R = rp / nr;

        float zf; int ii;
        if (n == 0)        { zf = 1.0f; ii = 1; }
        else if (n <= NIN) { zf = z[b * NIN + n - 1]; ii = is_input[b * NIN + n - 1]; }
        else               { zf = 0.0f; ii = 0; }

        float V;
        if (ii > 0) {
            float x = __fmul_rn(PI_F, zf);
            V = __fadd_rn(__fmul_rn(-cosf(x), v0l), __fmul_rn(sinf(x), R));
        } else {
            V = R;
        }
        if (n == 0) V = v0l;
        V_g[((size_t)b * 1024 + n) * 32 + l] = V;
    }

    // free list (warp 31)
    if (w == 31) {
        int m = 0;
        for (int base = 1; base < 1024; base += 32) {
            int n = base + l;
            bool f = (n < 1024) && (n > NIN || is_input[b * NIN + n - 1] == 0);
            unsigned msk = __ballot_sync(0xffffffffu, f);
            if (f) {
                int pos = m + __popc(msk & ((1u << l) - 1u));
                list_g[b * 1024 + pos] = (unsigned short)n;
            }
            m += __popc(msk);
        }
        if (l == 0) cnt_g[b] = m;
    }
    __syncthreads();

    // VH fill: VH[b][m] = V_init[b][lst[m]]
    int c = cnt_g[b];
    for (int m = w; m < c; m += 32) {
        int i = list_g[b * 1024 + m];
        VH_g[((size_t)b * 1024 + m) * 32 + l] = V_g[((size_t)b * 1024 + i) * 32 + l];
    }
}

// ---------------- mix kernel: 2-CTA cluster, S=8, 4-role mbarrier pipeline ----------------
// CTA0: warps 0-7 dots (rows 0..511), warp 8 reducer, warp 9 base-helper.
// CTA1: warps 0-7 dots (rows 512..1023), warp 8 pre-reducer, warp 9 idle.
__global__ void __launch_bounds__(320, 1) __cluster_dims__(2, 1, 1)
mix_kernel(const float* __restrict__ C,
           const float* __restrict__ z,
           const int* __restrict__ is_input,
           float* __restrict__ out) {
    extern __shared__ __align__(16) float sm[];
    unsigned short* lstS = (unsigned short*)&sm[F_LST];
    __shared__ __align__(8) unsigned long long mbPart[3];
    __shared__ __align__(8) unsigned long long mbVn[4];
    __shared__ __align__(8) unsigned long long mbBase[2];

    uint32_t rank;
    asm("mov.u32 %0, %%cluster_ctarank;" : "=r"(rank));
    const int b = blockIdx.x >> 1;
    const int tid = threadIdx.x;
    const int w = tid >> 5;           // 0..9
    const int l = tid & 31;
    const bool dotw = (w < 8);
    const bool redw = (rank == 0) && (w == 8);
    const bool prew = (rank == 1) && (w == 8);
    const bool helw = (rank == 0) && (w == 9);
    const uint32_t smb = smem_u32(sm);
    const uint32_t mbPartA = smem_u32(mbPart);
    const uint32_t mbVnA = smem_u32(mbVn);
    const uint32_t mbBaseA = smem_u32(mbBase);

    __shared__ int scnt;
    for (int idx = tid; idx < 1024; idx += 320)
        lstS[idx] = list_g[b * 1024 + idx];
    if (tid == 0) {
        scnt = cnt_g[b];
        mbar_init(mbPartA + 0, rank == 0 ? 288u : 256u);
        mbar_init(mbPartA + 8, rank == 0 ? 288u : 256u);
        mbar_init(mbPartA + 16, rank == 0 ? 288u : 256u);
        mbar_init(mbVnA + 0, 32u);
        mbar_init(mbVnA + 8, 32u);
        mbar_init(mbVnA + 16, 32u);
        mbar_init(mbVnA + 24, 32u);
        mbar_init(mbBaseA + 0, 32u);
        mbar_init(mbBaseA + 8, 32u);
    }
    // zero dv ring slots 2,3 (read as dv(-2), dv(-1) with zero effect)
    if (rank == 0) {
        for (int idx = tid; idx < 1024; idx += 320)
            sm[F_DVB + idx] = 0.0f;
    }
    __syncthreads();
    const int cnt = scnt;
    const int total = cnt * SWEEPS;
    const int P = (total + S - 1) / S;

    // coupling tables (CTA0 only): svd[d][m] = C[lst[(m+d+1)%cnt], lst[m]], dist 1..23
    if (rank == 0) {
        for (int t = tid; t < 23 * cnt; t += 320) {
            int d = t / cnt;
            int m = t - d * cnt;
            int mp = m + d + 1; if (mp >= cnt) mp -= cnt;
            sm[F_SVD + d * 1024 + m] =
                __ldg(C + (size_t)lstS[mp] * NVARS + lstS[m]);
        }
    }

    // V registers: CTA rank owns rows [512*rank, +512), warp w -> 64 rows
    unsigned long long v2[32];
    const int rowbase = (int)rank * 512 + w * 64;
    if (dotw) {
#pragma unroll
        for (int p = 0; p < 32; p++) {
            int row = rowbase + 2 * p;
            v2[p] = pk2(V_g[((size_t)b * 1024 + row) * 32 + l],
                        V_g[((size_t)b * 1024 + row + 1) * 32 + l]);
        }
    }

    // staging: tid<256: half-row s = tid>>5 (0..7), 4 chunks of 16B
    const int st_s = tid >> 5;
    const int st_c = (tid & 31) * 4;

    // prologue staging: group 0 -> slot 0, group 1 -> slot 1
    if (tid < 256) {
        const float* src = C + (size_t)lstS[st_s] * NVARS + rank * 512;
        float* dst = &sm[F_CBUF + (0 * 8 + st_s) * 512];
#pragma unroll
        for (int c4 = 0; c4 < 4; c4++)
            __pipeline_memcpy_async(dst + st_c + c4 * 128, src + st_c + c4 * 128, 16);
    }
    __pipeline_commit();
    if (tid < 256) {
        int mq = (S + st_s) % cnt;
        const float* src = C + (size_t)lstS[mq] * NVARS + rank * 512;
        float* dst = &sm[F_CBUF + (1 * 8 + st_s) * 512];
#pragma unroll
        for (int c4 = 0; c4 < 4; c4++)
            __pipeline_memcpy_async(dst + st_c + c4 * 128, src + st_c + c4 * 128, 16);
    }
    __pipeline_commit();

    __syncthreads();       // svd + lst + mbarrier init + dv-zero visible intra-CTA
    CLUSTER_SYNC();        // cluster-wide visibility before remote arrives

    // ================= role loops =================
    if (dotw) {
        int m_stage = (2 * S) % cnt;     // base of group k+2
        int m_app = 0;                   // base of group k-3
        for (int k = 0; k < P; k++) {
            if (k >= 3) {
                int g = k - 3;
                mbar_wait(mbVnA + (g & 3) * 8, (unsigned)((g >> 2) & 1));
#pragma unroll
                for (int s = 0; s < S; s++) {
                    int mp = m_app + s; if (mp >= cnt) mp -= cnt;
                    int i = lstS[mp];
                    if ((i >> 6) == (int)rank * 8 + w)
                        insert_pred(v2, i & 63, sm[F_VNB + (g & 3) * 256 + s * 32 + l]);
                }
                m_app += S; if (m_app >= cnt) m_app -= cnt;
            }
            __pipeline_wait_prior(1);
            asm volatile("bar.sync 1, 256;" ::: "memory");
            {
                int mq = m_stage + st_s; if (mq >= cnt) mq -= cnt;
                const float* src = C + (size_t)lstS[mq] * NVARS + rank * 512;
                float* dst = &sm[F_CBUF + (((k + 2) % 3) * 8 + st_s) * 512];
#pragma unroll
                for (int c4 = 0; c4 < 4; c4++)
                    __pipeline_memcpy_async(dst + st_c + c4 * 128, src + st_c + c4 * 128, 16);
                __pipeline_commit();
                m_stage += S; if (m_stage >= cnt) m_stage -= cnt;
            }
            int slotc = (k % 3) * 8;
            int slotp = (k % 3) * 2048;
#pragma unroll
            for (int s = 0; s < S; s++) {
                const ulonglong2* Cs = reinterpret_cast<const ulonglong2*>(
                    &sm[F_CBUF + (slotc + s) * 512 + w * 64]);
                sm[F_PT + slotp + s * 256 + w * 32 + l] = dot_row(Cs, v2);
            }
            mbar_arrive_local(mbPartA + (k % 3) * 8);
        }
        // drain: apply vn(P-3..P-1)
        for (int g = (P >= 3 ? P - 3 : 0); g < P; g++) {
            mbar_wait(mbVnA + (g & 3) * 8, (unsigned)((g >> 2) & 1));
#pragma unroll
            for (int s = 0; s < S; s++) {
                if (g * S + s < total) {
                    int mp = m_app + s; if (mp >= cnt) mp -= cnt;
                    int i = lstS[mp];
                    if ((i >> 6) == (int)rank * 8 + w)
                        insert_pred(v2, i & 63, sm[F_VNB + (g & 3) * 256 + s * 32 + l]);
                }
            }
            m_app += S; if (m_app >= cnt) m_app -= cnt;
        }
        __pipeline_wait_prior(0);
    } else if (prew) {
        // CTA1 pre-reducer
        int s3 = 0; unsigned p3v = 0;
        for (int k = 0; k < P; k++) {
            mbar_wait(mbPartA + s3 * 8, p3v);
            int slotp = s3 * 2048;
#pragma unroll
            for (int s = 0; s < S; s++) {
                const float* pr = &sm[F_PT + slotp + s * 256];
                float t0 = pr[0*32+l], t1 = pr[1*32+l], t2 = pr[2*32+l], t3 = pr[3*32+l];
                float t4 = pr[4*32+l], t5 = pr[5*32+l], t6 = pr[6*32+l], t7 = pr[7*32+l];
                float rs = ((t0 + t1) + (t2 + t3)) + ((t4 + t5) + (t6 + t7));
                sts_remote(smb + (F_RSUM + s3 * 256 + s * 32 + l) * 4, 0, rs);
            }
            mbar_arrive_remote(mbPartA + s3 * 8, 0);
            s3++; if (s3 == 3) { s3 = 0; p3v ^= 1u; }
        }
    } else if (helw) {
        // CTA0 base-helper: base(k) = tree(k) + rsum(k) + dv(k-2)-corrections
        int s3 = 0; unsigned p3v = 0;
        int m_km2 = 0;                         // base of group k-2 (valid from k=2)
        for (int k = 0; k < P; k++) {
            mbar_wait(mbPartA + s3 * 8, p3v);
            float dvb[S];
            if (k >= 2) {
                mbar_wait(mbVnA + ((k - 2) & 3) * 8, (unsigned)(((k - 2) >> 2) & 1));
#pragma unroll
                for (int sp = 0; sp < S; sp++)
                    dvb[sp] = sm[F_DVB + ((k - 2) & 3) * 256 + sp * 32 + l];
            } else {
#pragma unroll
                for (int sp = 0; sp < S; sp++) dvb[sp] = 0.0f;
            }
            int slotp = s3 * 2048;
#pragma unroll
            for (int s = 0; s < S; s++) {
                const float* pr = &sm[F_PT + slotp + s * 256];
                float t0 = pr[0*32+l], t1 = pr[1*32+l], t2 = pr[2*32+l], t3 = pr[3*32+l];
                float t4 = pr[4*32+l], t5 = pr[5*32+l], t6 = pr[6*32+l], t7 = pr[7*32+l];
                float g = ((t0 + t1) + (t2 + t3)) + ((t4 + t5) + (t6 + t7));
                g += sm[F_RSUM + s3 * 256 + s * 32 + l];
                if (k >= 2) {
#pragma unroll
                    for (int sp = 0; sp < S; sp++) {
                        int d2 = 2 * S + s - sp;        // 9..23
                        int mq2 = m_km2 + sp; if (mq2 >= cnt) mq2 -= cnt;
                        g = fmaf(sm[F_SVD + (d2 - 1) * 1024 + mq2], dvb[sp], g);
                    }
                }
                sm[F_BASE + (k & 1) * 256 + s * 32 + l] = g;
            }
            mbar_arrive_local(mbBaseA + (k & 1) * 8);
            if (k >= 2) { m_km2 += S; if (m_km2 >= cnt) m_km2 -= cnt; }
            s3++; if (s3 == 3) { s3 = 0; p3v ^= 1u; }
        }
    } else if (redw) {
        // CTA0 reducer: dv(k-1) fold + intra chain + normalize only
        float dvP1[S], vold_cur[S], vnq[S];
#pragma unroll
        for (int s = 0; s < S; s++) {
            dvP1[s] = 0.f;
            vold_cur[s] = VH_g[((size_t)b * 1024 + s) * 32 + l];
        }
        int m_prev = 0, m_cur = 0, m_n1 = S % cnt;
        for (int k = 0; k < P; k++) {
            mbar_wait(mbBaseA + (k & 1) * 8, (unsigned)((k >> 1) & 1));
            float vold_nxt[S];
#pragma unroll
            for (int s = 0; s < S; s++) {
                int mq = m_n1 + s; if (mq >= cnt) mq -= cnt;
                vold_nxt[s] = VH_g[((size_t)b * 1024 + mq) * 32 + l];
            }
            // fold dv(k-1) into base (independent of serial chain)
            float b2[S];
#pragma unroll
            for (int s = 0; s < S; s++) {
                float g = sm[F_BASE + (k & 1) * 256 + s * 32 + l];
#pragma unroll
                for (int sp = 0; sp < S; sp++) {
                    int d1 = S + s - sp;                // 1..15
                    int mq1 = m_prev + sp; if (mq1 >= cnt) mq1 -= cnt;
                    g = fmaf(sm[F_SVD + (d1 - 1) * 1024 + mq1], dvP1[sp], g);
                }
                b2[s] = g;
            }
            // serial chain
            float dv_new[S];
#pragma unroll
            for (int s = 0; s < S; s++) {
                float g = b2[s];
#pragma unroll
                for (int sp = 0; sp < S; sp++)
                    if (sp < s) {
                        int d = s - sp;                 // 1..7
                        int mq = m_cur + sp; if (mq >= cnt) mq -= cnt;
                        g = fmaf(sm[F_SVD + (d - 1) * 1024 + mq], dv_new[sp], g);
                    }
                float ss = warp_sum(g * g);
                ss = fmaxf(ss, 1e-24f);
                float vn = -g * rsqrtf(ss);
                vnq[s] = vn;
                dv_new[s] = vn - vold_cur[s];
            }
            // publish: local VNB + DVB, VH, then arrives; remote vn batch
#pragma unroll
            for (int s = 0; s < S; s++) {
                sm[F_VNB + (k & 3) * 256 + s * 32 + l] = vnq[s];
                sm[F_DVB + (k & 3) * 256 + s * 32 + l] = dv_new[s];
                int mq = m_cur + s; if (mq >= cnt) mq -= cnt;
                VH_g[((size_t)b * 1024 + mq) * 32 + l] = vnq[s];
            }
#pragma unroll
            for (int s = 0; s < S; s++)
                sts_remote(smb + (F_VNB + (k & 3) * 256 + s * 32 + l) * 4, 1, vnq[s]);
            mbar_arrive_local(mbVnA + (k & 3) * 8);
            mbar_arrive_remote(mbVnA + (k & 3) * 8, 1);
#pragma unroll
            for (int s = 0; s < S; s++) { dvP1[s] = dv_new[s]; vold_cur[s] = vold_nxt[s]; }
            m_prev = m_cur; m_cur = m_n1;
            m_n1 += S; if (m_n1 >= cnt) m_n1 -= cnt;
        }
    }

    CLUSTER_SYNC();

    // ---------------- epilogue: z_out[:, 1:769] ----------------
    if (dotw) {
        float v0l = v0_g[b * 32 + l];
        const float CLO = (float)(-1.0 + 1e-7);
        const float CHI = (float)( 1.0 - 1e-7);
#pragma unroll
        for (int j = 0; j < 64; j++) {
            int n = rowbase + j;
            if (n >= 1 && n <= NIN) {
                float x, y; up2(v2[j >> 1], x, y);
                float Vv = (j & 1) ? y : x;
                float d = warp_sum(__fmul_rn(Vv, v0l));
                if (l == 0) {
                    int idx = b * NIN + n - 1;
                    float res;
                    if (is_input[idx] != 0) {
                        res = z[idx];
                    } else {
                        float ca = fminf(fmaxf(-d, CLO), CHI);
                        res = acosf(ca) / PI_F;
                    }
                    out[idx] = res;
                }
            }
        }
    }
}

// ---------------- launcher ----------------
extern "C" void kernel_launch(void* const* d_in, const int* in_sizes, int n_in,
                              void* d_out, int out_size) {
    const float* C        = (const float*)d_in[0];
    const float* z        = (const float*)d_in[1];
    const int*   is_input = (const int*)d_in[2];
    float* out = (float*)d_out;

    cudaFuncSetAttribute(mix_kernel,
                         cudaFuncAttributeMaxDynamicSharedMemorySize, SMEM_BYTES);

    init_kernel<<<BATCH, 1024>>>(z, is_input);
    mix_kernel<<<2 * BATCH, 320, SMEM_BYTES>>>(C, z, is_input, out);
}